// round 1
// baseline (speedup 1.0000x reference)
#include <cuda_runtime.h>

#define B_  2
#define T_  2048
#define D_  1024
#define H_  16
#define HD_ 64
#define M_  (B_*T_)   // 4096

// Scratch (allocation-free rule: __device__ globals)
__device__ float g_q[M_*D_];
__device__ float g_k[M_*D_];
__device__ float g_v[M_*D_];
__device__ float g_wv[M_*D_];
__device__ float g_rmax[B_*H_*T_];
__device__ float g_rinv[B_*H_*T_];

// Fast exp on the FMA pipe (avoids MUFU.EX2 throughput wall).
// 2^y with y = x*log2(e); magic-number split, degree-5 Taylor on f in [-0.5,0.5].
// Max rel error ~2.4e-6. Handles x ~ -1e9 (masked logits) via clamp -> ~2^-126 ~ 0.
__device__ __forceinline__ float fexp(float x) {
    float y = fmaxf(x * 1.44269504f, -126.0f);
    float z = y + 12582912.0f;                    // 1.5 * 2^23
    int   n = __float_as_int(z) - 0x4B400000;
    float f = y - (z - 12582912.0f);              // f in [-0.5, 0.5]
    float p = 1.3333558e-3f;
    p = fmaf(p, f, 9.6181291e-3f);
    p = fmaf(p, f, 5.5504109e-2f);
    p = fmaf(p, f, 2.4022651e-1f);
    p = fmaf(p, f, 6.9314718e-1f);
    p = fmaf(p, f, 1.0f);
    return p * __int_as_float((n << 23) + 0x3F800000);
}

// ---------------------------------------------------------------------------
// GEMM (NT): C[M,N] = A[M,K] @ W[N,K]^T + bias.  Fixed M=4096, N=K=1024.
// 64x64 block tile, BK=32, 256 threads, 4x4 per thread.
// csel: 0->g_q 1->g_k 2->g_v else Cext.  A==nullptr -> g_wv.
// ---------------------------------------------------------------------------
__global__ void __launch_bounds__(256) gemm_nt_bias(
    const float* __restrict__ A, const float* __restrict__ W,
    const float* __restrict__ bias, float* __restrict__ Cext, int csel)
{
    if (A == nullptr) A = g_wv;
    float* C = (csel == 0) ? g_q : (csel == 1) ? g_k : (csel == 2) ? g_v : Cext;

    __shared__ __align__(16) float As[32][68];
    __shared__ __align__(16) float Bs[32][68];

    const int tid = threadIdx.x;
    const int ty = tid >> 4, tx = tid & 15;
    const int bm = blockIdx.y << 6, bn = blockIdx.x << 6;

    float acc[4][4] = {};

    for (int k0 = 0; k0 < D_; k0 += 32) {
        #pragma unroll
        for (int i = 0; i < 2; i++) {
            int idx = tid + (i << 8);
            int r = idx >> 3, cg = idx & 7;
            float4 av = *(const float4*)&A[(size_t)(bm + r) * D_ + k0 + (cg << 2)];
            As[(cg << 2) + 0][r] = av.x; As[(cg << 2) + 1][r] = av.y;
            As[(cg << 2) + 2][r] = av.z; As[(cg << 2) + 3][r] = av.w;
            float4 wv = *(const float4*)&W[(size_t)(bn + r) * D_ + k0 + (cg << 2)];
            Bs[(cg << 2) + 0][r] = wv.x; Bs[(cg << 2) + 1][r] = wv.y;
            Bs[(cg << 2) + 2][r] = wv.z; Bs[(cg << 2) + 3][r] = wv.w;
        }
        __syncthreads();
        #pragma unroll
        for (int k = 0; k < 32; k++) {
            float4 a = *(const float4*)&As[k][ty << 2];
            float4 b = *(const float4*)&Bs[k][tx << 2];
            float ar[4] = {a.x, a.y, a.z, a.w};
            float br[4] = {b.x, b.y, b.z, b.w};
            #pragma unroll
            for (int i = 0; i < 4; i++)
                #pragma unroll
                for (int j = 0; j < 4; j++)
                    acc[i][j] = fmaf(ar[i], br[j], acc[i][j]);
        }
        __syncthreads();
    }

    float4 bb = make_float4(0.f, 0.f, 0.f, 0.f);
    if (bias) bb = *(const float4*)&bias[bn + (tx << 2)];
    #pragma unroll
    for (int i = 0; i < 4; i++) {
        int m = bm + (ty << 2) + i;
        float4 o = make_float4(acc[i][0] + bb.x, acc[i][1] + bb.y,
                               acc[i][2] + bb.z, acc[i][3] + bb.w);
        *(float4*)&C[(size_t)m * D_ + bn + (tx << 2)] = o;
    }
}

// ---------------------------------------------------------------------------
// RoPE (in-place, pairwise) + scale by HD^-0.25 on q (which=0) or k (which=1).
// ---------------------------------------------------------------------------
__global__ void __launch_bounds__(256) rope_kernel(
    const float* __restrict__ cosp, const float* __restrict__ sinp, int which)
{
    float* q = which ? g_k : g_q;
    int idx = blockIdx.x * 256 + threadIdx.x;      // over M_*512 pairs
    int m = idx >> 9, pr = idx & 511;
    int t = m & (T_ - 1);
    int p = pr & 31;                                // pair index within head
    float c = cosp[t * 32 + p], s = sinp[t * 32 + p];
    float2* base = (float2*)(q + (size_t)m * D_ + pr * 2);
    float2 ab = *base;
    const float scale = 0.35355339059327373f;       // 64^-0.25
    float2 o;
    o.x = (ab.x * c - ab.y * s) * scale;
    o.y = (ab.x * s + ab.y * c) * scale;
    *base = o;
}

// ---------------------------------------------------------------------------
// qk[bh,t,s] = q[b,t,h,:] . k[b,s,h,:] + (s>t ? -1e9 : 0)
// One 64x64 output tile per block, K=64 single stage.
// ---------------------------------------------------------------------------
__global__ void __launch_bounds__(256) qk_kernel(float* __restrict__ qkout)
{
    __shared__ __align__(16) float Qs[64][68];
    __shared__ __align__(16) float Ks[64][68];

    const int tid = threadIdx.x;
    const int ty = tid >> 4, tx = tid & 15;
    const int bh = blockIdx.z;
    const int b = bh >> 4, h = bh & 15;
    const int t0 = blockIdx.y << 6, s0 = blockIdx.x << 6;

    const float* Q = g_q + (size_t)b * T_ * D_ + h * HD_;
    const float* K = g_k + (size_t)b * T_ * D_ + h * HD_;

    #pragma unroll
    for (int i = 0; i < 4; i++) {
        int idx = tid + (i << 8);
        int r = idx >> 4, cg = idx & 15;
        float4 qv = *(const float4*)&Q[(size_t)(t0 + r) * D_ + (cg << 2)];
        Qs[(cg << 2) + 0][r] = qv.x; Qs[(cg << 2) + 1][r] = qv.y;
        Qs[(cg << 2) + 2][r] = qv.z; Qs[(cg << 2) + 3][r] = qv.w;
        float4 kv = *(const float4*)&K[(size_t)(s0 + r) * D_ + (cg << 2)];
        Ks[(cg << 2) + 0][r] = kv.x; Ks[(cg << 2) + 1][r] = kv.y;
        Ks[(cg << 2) + 2][r] = kv.z; Ks[(cg << 2) + 3][r] = kv.w;
    }
    __syncthreads();

    float acc[4][4] = {};
    #pragma unroll
    for (int k = 0; k < 64; k++) {
        float4 a = *(const float4*)&Qs[k][ty << 2];
        float4 b4 = *(const float4*)&Ks[k][tx << 2];
        float ar[4] = {a.x, a.y, a.z, a.w};
        float br[4] = {b4.x, b4.y, b4.z, b4.w};
        #pragma unroll
        for (int i = 0; i < 4; i++)
            #pragma unroll
            for (int j = 0; j < 4; j++)
                acc[i][j] = fmaf(ar[i], br[j], acc[i][j]);
    }

    #pragma unroll
    for (int i = 0; i < 4; i++) {
        int t = t0 + (ty << 2) + i;
        int sb = s0 + (tx << 2);
        float4 o;
        o.x = acc[i][0] + ((sb + 0 > t) ? -1000000000.0f : 0.0f);
        o.y = acc[i][1] + ((sb + 1 > t) ? -1000000000.0f : 0.0f);
        o.z = acc[i][2] + ((sb + 2 > t) ? -1000000000.0f : 0.0f);
        o.w = acc[i][3] + ((sb + 3 > t) ? -1000000000.0f : 0.0f);
        *(float4*)&qkout[((size_t)bh * T_ + t) * T_ + sb] = o;
    }
}

// ---------------------------------------------------------------------------
// Per-row softmax stats: row max + 1/sum(exp). One block per (bh,t) row.
// ---------------------------------------------------------------------------
__global__ void __launch_bounds__(256) softstats_kernel(const float* __restrict__ qk)
{
    __shared__ float red[256];
    const int row = blockIdx.x;
    const int tid = threadIdx.x;
    const float4* p = (const float4*)(qk + (size_t)row * T_);

    float4 v0 = p[tid], v1 = p[tid + 256];
    float m = fmaxf(fmaxf(fmaxf(v0.x, v0.y), fmaxf(v0.z, v0.w)),
                    fmaxf(fmaxf(v1.x, v1.y), fmaxf(v1.z, v1.w)));
    red[tid] = m;
    __syncthreads();
    for (int s = 128; s > 0; s >>= 1) {
        if (tid < s) red[tid] = fmaxf(red[tid], red[tid + s]);
        __syncthreads();
    }
    m = red[0];
    __syncthreads();

    float sum = fexp(v0.x - m) + fexp(v0.y - m) + fexp(v0.z - m) + fexp(v0.w - m)
              + fexp(v1.x - m) + fexp(v1.y - m) + fexp(v1.z - m) + fexp(v1.w - m);
    red[tid] = sum;
    __syncthreads();
    for (int s = 128; s > 0; s >>= 1) {
        if (tid < s) red[tid] += red[tid + s];
        __syncthreads();
    }
    if (tid == 0) { g_rmax[row] = m; g_rinv[row] = 1.0f / red[0]; }
}

// ---------------------------------------------------------------------------
// wv[b,t,h,:] = sum_s softmax(qk)[bh,t,s] * v[b,s,h,:]
// exp applied at tile-load, 1/sum deferred to epilogue.
// ---------------------------------------------------------------------------
__global__ void __launch_bounds__(256) wv_kernel(const float* __restrict__ qk)
{
    __shared__ __align__(16) float Ps[64][68];
    __shared__ __align__(16) float Vs[64][68];
    __shared__ float mrow[64];

    const int tid = threadIdx.x;
    const int ty = tid >> 4, tx = tid & 15;
    const int bh = blockIdx.y;
    const int b = bh >> 4, h = bh & 15;
    const int t0 = blockIdx.x << 6;

    const float* P = qk + ((size_t)bh * T_ + t0) * T_;
    const float* V = g_v + (size_t)b * T_ * D_ + h * HD_;

    if (tid < 64) mrow[tid] = g_rmax[bh * T_ + t0 + tid];
    __syncthreads();

    float acc[4][4] = {};
    for (int s0 = 0; s0 < T_; s0 += 64) {
        #pragma unroll
        for (int i = 0; i < 4; i++) {
            int idx = tid + (i << 8);
            int r = idx >> 4, cg = idx & 15;
            float mr = mrow[r];
            float4 pv = *(const float4*)&P[(size_t)r * T_ + s0 + (cg << 2)];
            Ps[(cg << 2) + 0][r] = fexp(pv.x - mr);
            Ps[(cg << 2) + 1][r] = fexp(pv.y - mr);
            Ps[(cg << 2) + 2][r] = fexp(pv.z - mr);
            Ps[(cg << 2) + 3][r] = fexp(pv.w - mr);
            float4 vv = *(const float4*)&V[(size_t)(s0 + r) * D_ + (cg << 2)];
            *(float4*)&Vs[r][cg << 2] = vv;
        }
        __syncthreads();
        #pragma unroll
        for (int k = 0; k < 64; k++) {
            float4 a = *(const float4*)&Ps[k][ty << 2];
            float4 b4 = *(const float4*)&Vs[k][tx << 2];
            float ar[4] = {a.x, a.y, a.z, a.w};
            float br[4] = {b4.x, b4.y, b4.z, b4.w};
            #pragma unroll
            for (int i = 0; i < 4; i++)
                #pragma unroll
                for (int j = 0; j < 4; j++)
                    acc[i][j] = fmaf(ar[i], br[j], acc[i][j]);
        }
        __syncthreads();
    }

    #pragma unroll
    for (int i = 0; i < 4; i++) {
        int t = t0 + (ty << 2) + i;
        float ri = g_rinv[bh * T_ + t];
        float4 o = make_float4(acc[i][0] * ri, acc[i][1] * ri,
                               acc[i][2] * ri, acc[i][3] * ri);
        *(float4*)&g_wv[(size_t)(b * T_ + t) * D_ + h * HD_ + (tx << 2)] = o;
    }
}

// ---------------------------------------------------------------------------
// Inputs: x, mask, cos, sin, Wq, bq, Wk, Wv, bv, Wo, bo
// Output: [out (B,T,D) | qk (B,H,T,T)] fp32, concatenated.
// ---------------------------------------------------------------------------
extern "C" void kernel_launch(void* const* d_in, const int* in_sizes, int n_in,
                              void* d_out, int out_size)
{
    const float* x    = (const float*)d_in[0];
    const float* cosp = (const float*)d_in[2];
    const float* sinp = (const float*)d_in[3];
    const float* Wq   = (const float*)d_in[4];
    const float* bq   = (const float*)d_in[5];
    const float* Wk   = (const float*)d_in[6];
    const float* Wv   = (const float*)d_in[7];
    const float* bv   = (const float*)d_in[8];
    const float* Wo   = (const float*)d_in[9];
    const float* bo   = (const float*)d_in[10];

    float* out = (float*)d_out;
    float* qk  = out + (size_t)M_ * D_;

    dim3 gg(D_ / 64, M_ / 64);
    gemm_nt_bias<<<gg, 256>>>(x, Wq, bq, nullptr, 0);
    gemm_nt_bias<<<gg, 256>>>(x, Wk, nullptr, nullptr, 1);
    gemm_nt_bias<<<gg, 256>>>(x, Wv, bv, nullptr, 2);

    rope_kernel<<<M_ * 512 / 256, 256>>>(cosp, sinp, 0);
    rope_kernel<<<M_ * 512 / 256, 256>>>(cosp, sinp, 1);

    dim3 gqk(T_ / 64, T_ / 64, B_ * H_);
    qk_kernel<<<gqk, 256>>>(qk);

    softstats_kernel<<<B_ * H_ * T_, 256>>>(qk);

    dim3 gwv(T_ / 64, B_ * H_);
    wv_kernel<<<gwv, 256>>>(qk);

    gemm_nt_bias<<<gg, 256>>>(nullptr, Wo, bo, out, 3);
}

// round 2
// speedup vs baseline: 1.2904x; 1.2904x over previous
#include <cuda_runtime.h>
#include <cuda_bf16.h>
#include <cstdint>

#define B_  2
#define T_  2048
#define D_  1024
#define H_  16
#define HD_ 64
#define M_  (B_*T_)   // 4096

// Scratch (allocation-free rule: __device__ globals)
__device__ float g_q[M_*D_];
__device__ float g_k[M_*D_];
__device__ float g_v[M_*D_];
__device__ float g_wv[M_*D_];
__device__ float g_rmax[B_*H_*T_];
__device__ float g_rinv[B_*H_*T_];

// Fast exp on the FMA pipe (avoids MUFU.EX2 throughput wall).
__device__ __forceinline__ float fexp(float x) {
    float y = fmaxf(x * 1.44269504f, -126.0f);
    float z = y + 12582912.0f;                    // 1.5 * 2^23
    int   n = __float_as_int(z) - 0x4B400000;
    float f = y - (z - 12582912.0f);              // f in [-0.5, 0.5]
    float p = 1.3333558e-3f;
    p = fmaf(p, f, 9.6181291e-3f);
    p = fmaf(p, f, 5.5504109e-2f);
    p = fmaf(p, f, 2.4022651e-1f);
    p = fmaf(p, f, 6.9314718e-1f);
    p = fmaf(p, f, 1.0f);
    return p * __int_as_float((n << 23) + 0x3F800000);
}

// ---------------------------------------------------------------------------
// Tensor-core dense GEMM (NT): C[M,N] = A[M,K] @ W[N,K]^T + bias
// bf16x3 split (Ah*Bh + Ah*Bl + Al*Bh), fp32 accumulate via mma.sync m16n8k16.
// Block tile 128(M) x 64(N), K-step 32. 256 threads = 8 warps (4x2),
// warp tile 32x32 = 2 m16-tiles x 4 n8-tiles.
// csel: 0->g_q 1->g_k 2->g_v else Cext.  A==nullptr -> g_wv.
// ---------------------------------------------------------------------------
#define PITCH 40   // bf16 units per smem row (20 words -> conflict-free frag loads)

__device__ __forceinline__ void mma_bf16(float* c, const uint32_t* a, const uint32_t* b) {
    asm volatile(
        "mma.sync.aligned.m16n8k16.row.col.f32.bf16.bf16.f32 "
        "{%0,%1,%2,%3}, {%4,%5,%6,%7}, {%8,%9}, {%0,%1,%2,%3};\n"
        : "+f"(c[0]), "+f"(c[1]), "+f"(c[2]), "+f"(c[3])
        : "r"(a[0]), "r"(a[1]), "r"(a[2]), "r"(a[3]), "r"(b[0]), "r"(b[1]));
}

__device__ __forceinline__ uint32_t lds2(const __nv_bfloat16* p, int r, int c) {
    return *(const uint32_t*)(p + r * PITCH + c);
}

__global__ void __launch_bounds__(256) gemm_tc(
    const float* __restrict__ A, const float* __restrict__ W,
    const float* __restrict__ bias, float* __restrict__ Cext, int csel)
{
    if (A == nullptr) A = g_wv;
    float* C = (csel == 0) ? g_q : (csel == 1) ? g_k : (csel == 2) ? g_v : Cext;

    __shared__ __align__(16) __nv_bfloat16 sAh[128 * PITCH];
    __shared__ __align__(16) __nv_bfloat16 sAl[128 * PITCH];
    __shared__ __align__(16) __nv_bfloat16 sBh[64 * PITCH];
    __shared__ __align__(16) __nv_bfloat16 sBl[64 * PITCH];

    const int tid  = threadIdx.x;
    const int lane = tid & 31;
    const int wid  = tid >> 5;
    const int wm   = (wid & 3) << 5;    // warp M offset (0,32,64,96)
    const int wn   = (wid >> 2) << 5;   // warp N offset (0,32)
    const int bm   = blockIdx.y << 7;   // 128
    const int bn   = blockIdx.x << 6;   // 64

    float acc[2][4][4] = {};            // [mt][nt][c0..c3]

    for (int k0 = 0; k0 < D_; k0 += 32) {
        // ---- fill smem: A tile 128x32, W tile 64x32, fp32 -> bf16 hi/lo ----
        #pragma unroll
        for (int i = 0; i < 4; i++) {           // 1024 float4 over A tile
            int fi = tid + (i << 8);
            int r = fi >> 3, kq = (fi & 7) << 2;
            float4 v = *(const float4*)&A[(size_t)(bm + r) * D_ + k0 + kq];
            __nv_bfloat16* ph = &sAh[r * PITCH + kq];
            __nv_bfloat16* pl = &sAl[r * PITCH + kq];
            float vv[4] = {v.x, v.y, v.z, v.w};
            #pragma unroll
            for (int j = 0; j < 4; j++) {
                __nv_bfloat16 hi = __float2bfloat16(vv[j]);
                ph[j] = hi;
                pl[j] = __float2bfloat16(vv[j] - __bfloat162float(hi));
            }
        }
        #pragma unroll
        for (int i = 0; i < 2; i++) {           // 512 float4 over W tile
            int fi = tid + (i << 8);
            int r = fi >> 3, kq = (fi & 7) << 2;
            float4 v = *(const float4*)&W[(size_t)(bn + r) * D_ + k0 + kq];
            __nv_bfloat16* ph = &sBh[r * PITCH + kq];
            __nv_bfloat16* pl = &sBl[r * PITCH + kq];
            float vv[4] = {v.x, v.y, v.z, v.w};
            #pragma unroll
            for (int j = 0; j < 4; j++) {
                __nv_bfloat16 hi = __float2bfloat16(vv[j]);
                ph[j] = hi;
                pl[j] = __float2bfloat16(vv[j] - __bfloat162float(hi));
            }
        }
        __syncthreads();

        // ---- compute: two k16 sub-steps ----
        #pragma unroll
        for (int ks = 0; ks < 32; ks += 16) {
            const int ar = wm + (lane >> 2);
            const int ac = ks + ((lane & 3) << 1);
            uint32_t ah[2][4], al[2][4];
            #pragma unroll
            for (int mt = 0; mt < 2; mt++) {
                int r = ar + (mt << 4);
                ah[mt][0] = lds2(sAh, r,     ac);
                ah[mt][1] = lds2(sAh, r + 8, ac);
                ah[mt][2] = lds2(sAh, r,     ac + 8);
                ah[mt][3] = lds2(sAh, r + 8, ac + 8);
                al[mt][0] = lds2(sAl, r,     ac);
                al[mt][1] = lds2(sAl, r + 8, ac);
                al[mt][2] = lds2(sAl, r,     ac + 8);
                al[mt][3] = lds2(sAl, r + 8, ac + 8);
            }
            const int br = wn + (lane >> 2);
            uint32_t bh[4][2], bl[4][2];
            #pragma unroll
            for (int nt = 0; nt < 4; nt++) {
                int r = br + (nt << 3);
                bh[nt][0] = lds2(sBh, r, ac);
                bh[nt][1] = lds2(sBh, r, ac + 8);
                bl[nt][0] = lds2(sBl, r, ac);
                bl[nt][1] = lds2(sBl, r, ac + 8);
            }
            #pragma unroll
            for (int mt = 0; mt < 2; mt++)
                #pragma unroll
                for (int nt = 0; nt < 4; nt++) {
                    mma_bf16(acc[mt][nt], ah[mt], bh[nt]);
                    mma_bf16(acc[mt][nt], ah[mt], bl[nt]);
                    mma_bf16(acc[mt][nt], al[mt], bh[nt]);
                }
        }
        __syncthreads();
    }

    // ---- epilogue ----
    #pragma unroll
    for (int mt = 0; mt < 2; mt++) {
        int m0 = bm + wm + (mt << 4) + (lane >> 2);
        #pragma unroll
        for (int nt = 0; nt < 4; nt++) {
            int n0 = bn + wn + (nt << 3) + ((lane & 3) << 1);
            float b0 = 0.f, b1 = 0.f;
            if (bias) { b0 = bias[n0]; b1 = bias[n0 + 1]; }
            *(float2*)&C[(size_t)m0 * D_ + n0] =
                make_float2(acc[mt][nt][0] + b0, acc[mt][nt][1] + b1);
            *(float2*)&C[(size_t)(m0 + 8) * D_ + n0] =
                make_float2(acc[mt][nt][2] + b0, acc[mt][nt][3] + b1);
        }
    }
}

// ---------------------------------------------------------------------------
// RoPE (in-place, pairwise) + scale by HD^-0.25 on q (which=0) or k (which=1).
// ---------------------------------------------------------------------------
__global__ void __launch_bounds__(256) rope_kernel(
    const float* __restrict__ cosp, const float* __restrict__ sinp, int which)
{
    float* q = which ? g_k : g_q;
    int idx = blockIdx.x * 256 + threadIdx.x;      // over M_*512 pairs
    int m = idx >> 9, pr = idx & 511;
    int t = m & (T_ - 1);
    int p = pr & 31;                                // pair index within head
    float c = cosp[t * 32 + p], s = sinp[t * 32 + p];
    float2* base = (float2*)(q + (size_t)m * D_ + pr * 2);
    float2 ab = *base;
    const float scale = 0.35355339059327373f;       // 64^-0.25
    float2 o;
    o.x = (ab.x * c - ab.y * s) * scale;
    o.y = (ab.x * s + ab.y * c) * scale;
    *base = o;
}

// ---------------------------------------------------------------------------
// qk[bh,t,s] = q[b,t,h,:] . k[b,s,h,:] + (s>t ? -1e9 : 0)
// ---------------------------------------------------------------------------
__global__ void __launch_bounds__(256) qk_kernel(float* __restrict__ qkout)
{
    __shared__ __align__(16) float Qs[64][68];
    __shared__ __align__(16) float Ks[64][68];

    const int tid = threadIdx.x;
    const int ty = tid >> 4, tx = tid & 15;
    const int bh = blockIdx.z;
    const int b = bh >> 4, h = bh & 15;
    const int t0 = blockIdx.y << 6, s0 = blockIdx.x << 6;

    const float* Q = g_q + (size_t)b * T_ * D_ + h * HD_;
    const float* K = g_k + (size_t)b * T_ * D_ + h * HD_;

    #pragma unroll
    for (int i = 0; i < 4; i++) {
        int idx = tid + (i << 8);
        int r = idx >> 4, cg = idx & 15;
        float4 qv = *(const float4*)&Q[(size_t)(t0 + r) * D_ + (cg << 2)];
        Qs[(cg << 2) + 0][r] = qv.x; Qs[(cg << 2) + 1][r] = qv.y;
        Qs[(cg << 2) + 2][r] = qv.z; Qs[(cg << 2) + 3][r] = qv.w;
        float4 kv = *(const float4*)&K[(size_t)(s0 + r) * D_ + (cg << 2)];
        Ks[(cg << 2) + 0][r] = kv.x; Ks[(cg << 2) + 1][r] = kv.y;
        Ks[(cg << 2) + 2][r] = kv.z; Ks[(cg << 2) + 3][r] = kv.w;
    }
    __syncthreads();

    float acc[4][4] = {};
    #pragma unroll
    for (int k = 0; k < 64; k++) {
        float4 a = *(const float4*)&Qs[k][ty << 2];
        float4 b4 = *(const float4*)&Ks[k][tx << 2];
        float ar[4] = {a.x, a.y, a.z, a.w};
        float br[4] = {b4.x, b4.y, b4.z, b4.w};
        #pragma unroll
        for (int i = 0; i < 4; i++)
            #pragma unroll
            for (int j = 0; j < 4; j++)
                acc[i][j] = fmaf(ar[i], br[j], acc[i][j]);
    }

    #pragma unroll
    for (int i = 0; i < 4; i++) {
        int t = t0 + (ty << 2) + i;
        int sb = s0 + (tx << 2);
        float4 o;
        o.x = acc[i][0] + ((sb + 0 > t) ? -1000000000.0f : 0.0f);
        o.y = acc[i][1] + ((sb + 1 > t) ? -1000000000.0f : 0.0f);
        o.z = acc[i][2] + ((sb + 2 > t) ? -1000000000.0f : 0.0f);
        o.w = acc[i][3] + ((sb + 3 > t) ? -1000000000.0f : 0.0f);
        *(float4*)&qkout[((size_t)bh * T_ + t) * T_ + sb] = o;
    }
}

// ---------------------------------------------------------------------------
// Per-row softmax stats: row max + 1/sum(exp).
// ---------------------------------------------------------------------------
__global__ void __launch_bounds__(256) softstats_kernel(const float* __restrict__ qk)
{
    __shared__ float red[256];
    const int row = blockIdx.x;
    const int tid = threadIdx.x;
    const float4* p = (const float4*)(qk + (size_t)row * T_);

    float4 v0 = p[tid], v1 = p[tid + 256];
    float m = fmaxf(fmaxf(fmaxf(v0.x, v0.y), fmaxf(v0.z, v0.w)),
                    fmaxf(fmaxf(v1.x, v1.y), fmaxf(v1.z, v1.w)));
    red[tid] = m;
    __syncthreads();
    for (int s = 128; s > 0; s >>= 1) {
        if (tid < s) red[tid] = fmaxf(red[tid], red[tid + s]);
        __syncthreads();
    }
    m = red[0];
    __syncthreads();

    float sum = fexp(v0.x - m) + fexp(v0.y - m) + fexp(v0.z - m) + fexp(v0.w - m)
              + fexp(v1.x - m) + fexp(v1.y - m) + fexp(v1.z - m) + fexp(v1.w - m);
    red[tid] = sum;
    __syncthreads();
    for (int s = 128; s > 0; s >>= 1) {
        if (tid < s) red[tid] += red[tid + s];
        __syncthreads();
    }
    if (tid == 0) { g_rmax[row] = m; g_rinv[row] = 1.0f / red[0]; }
}

// ---------------------------------------------------------------------------
// wv[b,t,h,:] = sum_s softmax(qk)[bh,t,s] * v[b,s,h,:]
// ---------------------------------------------------------------------------
__global__ void __launch_bounds__(256) wv_kernel(const float* __restrict__ qk)
{
    __shared__ __align__(16) float Ps[64][68];
    __shared__ __align__(16) float Vs[64][68];
    __shared__ float mrow[64];

    const int tid = threadIdx.x;
    const int ty = tid >> 4, tx = tid & 15;
    const int bh = blockIdx.y;
    const int b = bh >> 4, h = bh & 15;
    const int t0 = blockIdx.x << 6;

    const float* P = qk + ((size_t)bh * T_ + t0) * T_;
    const float* V = g_v + (size_t)b * T_ * D_ + h * HD_;

    if (tid < 64) mrow[tid] = g_rmax[bh * T_ + t0 + tid];
    __syncthreads();

    float acc[4][4] = {};
    for (int s0 = 0; s0 < T_; s0 += 64) {
        #pragma unroll
        for (int i = 0; i < 4; i++) {
            int idx = tid + (i << 8);
            int r = idx >> 4, cg = idx & 15;
            float mr = mrow[r];
            float4 pv = *(const float4*)&P[(size_t)r * T_ + s0 + (cg << 2)];
            Ps[(cg << 2) + 0][r] = fexp(pv.x - mr);
            Ps[(cg << 2) + 1][r] = fexp(pv.y - mr);
            Ps[(cg << 2) + 2][r] = fexp(pv.z - mr);
            Ps[(cg << 2) + 3][r] = fexp(pv.w - mr);
            float4 vv = *(const float4*)&V[(size_t)(s0 + r) * D_ + (cg << 2)];
            *(float4*)&Vs[r][cg << 2] = vv;
        }
        __syncthreads();
        #pragma unroll
        for (int k = 0; k < 64; k++) {
            float4 a = *(const float4*)&Ps[k][ty << 2];
            float4 b4 = *(const float4*)&Vs[k][tx << 2];
            float ar[4] = {a.x, a.y, a.z, a.w};
            float br[4] = {b4.x, b4.y, b4.z, b4.w};
            #pragma unroll
            for (int i = 0; i < 4; i++)
                #pragma unroll
                for (int j = 0; j < 4; j++)
                    acc[i][j] = fmaf(ar[i], br[j], acc[i][j]);
        }
        __syncthreads();
    }

    #pragma unroll
    for (int i = 0; i < 4; i++) {
        int t = t0 + (ty << 2) + i;
        float ri = g_rinv[bh * T_ + t];
        float4 o = make_float4(acc[i][0] * ri, acc[i][1] * ri,
                               acc[i][2] * ri, acc[i][3] * ri);
        *(float4*)&g_wv[(size_t)(b * T_ + t) * D_ + h * HD_ + (tx << 2)] = o;
    }
}

// ---------------------------------------------------------------------------
// Inputs: x, mask, cos, sin, Wq, bq, Wk, Wv, bv, Wo, bo
// Output: [out (B,T,D) | qk (B,H,T,T)] fp32, concatenated.
// ---------------------------------------------------------------------------
extern "C" void kernel_launch(void* const* d_in, const int* in_sizes, int n_in,
                              void* d_out, int out_size)
{
    const float* x    = (const float*)d_in[0];
    const float* cosp = (const float*)d_in[2];
    const float* sinp = (const float*)d_in[3];
    const float* Wq   = (const float*)d_in[4];
    const float* bq   = (const float*)d_in[5];
    const float* Wk   = (const float*)d_in[6];
    const float* Wv   = (const float*)d_in[7];
    const float* bv   = (const float*)d_in[8];
    const float* Wo   = (const float*)d_in[9];
    const float* bo   = (const float*)d_in[10];

    float* out = (float*)d_out;
    float* qk  = out + (size_t)M_ * D_;

    dim3 gg(D_ / 64, M_ / 128);
    gemm_tc<<<gg, 256>>>(x, Wq, bq, nullptr, 0);
    gemm_tc<<<gg, 256>>>(x, Wk, nullptr, nullptr, 1);
    gemm_tc<<<gg, 256>>>(x, Wv, bv, nullptr, 2);

    rope_kernel<<<M_ * 512 / 256, 256>>>(cosp, sinp, 0);
    rope_kernel<<<M_ * 512 / 256, 256>>>(cosp, sinp, 1);

    dim3 gqk(T_ / 64, T_ / 64, B_ * H_);
    qk_kernel<<<gqk, 256>>>(qk);

    softstats_kernel<<<B_ * H_ * T_, 256>>>(qk);

    dim3 gwv(T_ / 64, B_ * H_);
    wv_kernel<<<gwv, 256>>>(qk);

    gemm_tc<<<gg, 256>>>(nullptr, Wo, bo, out, 3);
}

// round 3
// speedup vs baseline: 2.1153x; 1.6393x over previous
#include <cuda_runtime.h>
#include <cuda_bf16.h>
#include <cstdint>

#define B_  2
#define T_  2048
#define D_  1024
#define H_  16
#define HD_ 64
#define M_  (B_*T_)   // 4096

__device__ float g_q[M_*D_];
__device__ float g_k[M_*D_];
__device__ float g_v[M_*D_];
__device__ float g_wv[M_*D_];
__device__ float g_rmax[B_*H_*T_];
__device__ float g_rinv[B_*H_*T_];

// Fast exp on the FMA pipe.
__device__ __forceinline__ float fexp(float x) {
    float y = fmaxf(x * 1.44269504f, -126.0f);
    float z = y + 12582912.0f;
    int   n = __float_as_int(z) - 0x4B400000;
    float f = y - (z - 12582912.0f);
    float p = 1.3333558e-3f;
    p = fmaf(p, f, 9.6181291e-3f);
    p = fmaf(p, f, 5.5504109e-2f);
    p = fmaf(p, f, 2.4022651e-1f);
    p = fmaf(p, f, 6.9314718e-1f);
    p = fmaf(p, f, 1.0f);
    return p * __int_as_float((n << 23) + 0x3F800000);
}

#define PITCH 40   // bf16 per smem row: 20 words -> conflict-free frag loads

__device__ __forceinline__ void mma_bf16(float* c, const uint32_t* a, const uint32_t* b) {
    asm volatile(
        "mma.sync.aligned.m16n8k16.row.col.f32.bf16.bf16.f32 "
        "{%0,%1,%2,%3}, {%4,%5,%6,%7}, {%8,%9}, {%0,%1,%2,%3};\n"
        : "+f"(c[0]), "+f"(c[1]), "+f"(c[2]), "+f"(c[3])
        : "r"(a[0]), "r"(a[1]), "r"(a[2]), "r"(a[3]), "r"(b[0]), "r"(b[1]));
}

__device__ __forceinline__ uint32_t lds2(const __nv_bfloat16* p, int r, int c) {
    return *(const uint32_t*)(p + r * PITCH + c);
}

__device__ __forceinline__ void split_store(__nv_bfloat16* ph, __nv_bfloat16* pl, float v) {
    __nv_bfloat16 hi = __float2bfloat16(v);
    *ph = hi;
    *pl = __float2bfloat16(v - __bfloat162float(hi));
}

// ---------------------------------------------------------------------------
// Dense GEMM (NT): C = A @ W^T + bias.  128x64 tile, BK=32, bf16x3.
// ---------------------------------------------------------------------------
__global__ void __launch_bounds__(256) gemm_tc(
    const float* __restrict__ A, const float* __restrict__ W,
    const float* __restrict__ bias, float* __restrict__ Cext, int csel)
{
    if (A == nullptr) A = g_wv;
    float* C = (csel == 0) ? g_q : (csel == 1) ? g_k : (csel == 2) ? g_v : Cext;

    __shared__ __align__(16) __nv_bfloat16 sAh[128 * PITCH];
    __shared__ __align__(16) __nv_bfloat16 sAl[128 * PITCH];
    __shared__ __align__(16) __nv_bfloat16 sBh[64 * PITCH];
    __shared__ __align__(16) __nv_bfloat16 sBl[64 * PITCH];

    const int tid  = threadIdx.x;
    const int lane = tid & 31;
    const int wid  = tid >> 5;
    const int wm   = (wid & 3) << 5;
    const int wn   = (wid >> 2) << 5;
    const int bm   = blockIdx.y << 7;
    const int bn   = blockIdx.x << 6;

    float acc[2][4][4] = {};

    for (int k0 = 0; k0 < D_; k0 += 32) {
        #pragma unroll
        for (int i = 0; i < 4; i++) {
            int fi = tid + (i << 8);
            int r = fi >> 3, kq = (fi & 7) << 2;
            float4 v = *(const float4*)&A[(size_t)(bm + r) * D_ + k0 + kq];
            float vv[4] = {v.x, v.y, v.z, v.w};
            #pragma unroll
            for (int j = 0; j < 4; j++)
                split_store(&sAh[r * PITCH + kq + j], &sAl[r * PITCH + kq + j], vv[j]);
        }
        #pragma unroll
        for (int i = 0; i < 2; i++) {
            int fi = tid + (i << 8);
            int r = fi >> 3, kq = (fi & 7) << 2;
            float4 v = *(const float4*)&W[(size_t)(bn + r) * D_ + k0 + kq];
            float vv[4] = {v.x, v.y, v.z, v.w};
            #pragma unroll
            for (int j = 0; j < 4; j++)
                split_store(&sBh[r * PITCH + kq + j], &sBl[r * PITCH + kq + j], vv[j]);
        }
        __syncthreads();

        #pragma unroll
        for (int ks = 0; ks < 32; ks += 16) {
            const int ar = wm + (lane >> 2);
            const int ac = ks + ((lane & 3) << 1);
            uint32_t ah[2][4], al[2][4];
            #pragma unroll
            for (int mt = 0; mt < 2; mt++) {
                int r = ar + (mt << 4);
                ah[mt][0] = lds2(sAh, r, ac);     ah[mt][1] = lds2(sAh, r + 8, ac);
                ah[mt][2] = lds2(sAh, r, ac + 8); ah[mt][3] = lds2(sAh, r + 8, ac + 8);
                al[mt][0] = lds2(sAl, r, ac);     al[mt][1] = lds2(sAl, r + 8, ac);
                al[mt][2] = lds2(sAl, r, ac + 8); al[mt][3] = lds2(sAl, r + 8, ac + 8);
            }
            const int br = wn + (lane >> 2);
            uint32_t bh[4][2], bl[4][2];
            #pragma unroll
            for (int nt = 0; nt < 4; nt++) {
                int r = br + (nt << 3);
                bh[nt][0] = lds2(sBh, r, ac); bh[nt][1] = lds2(sBh, r, ac + 8);
                bl[nt][0] = lds2(sBl, r, ac); bl[nt][1] = lds2(sBl, r, ac + 8);
            }
            #pragma unroll
            for (int mt = 0; mt < 2; mt++)
                #pragma unroll
                for (int nt = 0; nt < 4; nt++) {
                    mma_bf16(acc[mt][nt], ah[mt], bh[nt]);
                    mma_bf16(acc[mt][nt], ah[mt], bl[nt]);
                    mma_bf16(acc[mt][nt], al[mt], bh[nt]);
                }
        }
        __syncthreads();
    }

    #pragma unroll
    for (int mt = 0; mt < 2; mt++) {
        int m0 = bm + wm + (mt << 4) + (lane >> 2);
        #pragma unroll
        for (int nt = 0; nt < 4; nt++) {
            int n0 = bn + wn + (nt << 3) + ((lane & 3) << 1);
            float b0 = 0.f, b1 = 0.f;
            if (bias) { b0 = bias[n0]; b1 = bias[n0 + 1]; }
            *(float2*)&C[(size_t)m0 * D_ + n0] =
                make_float2(acc[mt][nt][0] + b0, acc[mt][nt][1] + b1);
            *(float2*)&C[(size_t)(m0 + 8) * D_ + n0] =
                make_float2(acc[mt][nt][2] + b0, acc[mt][nt][3] + b1);
        }
    }
}

// ---------------------------------------------------------------------------
// RoPE (in-place) + scale by HD^-0.25.
// ---------------------------------------------------------------------------
__global__ void __launch_bounds__(256) rope_kernel(
    const float* __restrict__ cosp, const float* __restrict__ sinp, int which)
{
    float* q = which ? g_k : g_q;
    int idx = blockIdx.x * 256 + threadIdx.x;
    int m = idx >> 9, pr = idx & 511;
    int t = m & (T_ - 1);
    int p = pr & 31;
    float c = cosp[t * 32 + p], s = sinp[t * 32 + p];
    float2* base = (float2*)(q + (size_t)m * D_ + pr * 2);
    float2 ab = *base;
    const float scale = 0.35355339059327373f;
    float2 o;
    o.x = (ab.x * c - ab.y * s) * scale;
    o.y = (ab.x * s + ab.y * c) * scale;
    *base = o;
}

// ---------------------------------------------------------------------------
// qk via tensor cores: 128(t) x 64(s) tiles, K=64, bf16x3.
// Fully-masked tiles write -1e9 (per-element error ~1e-8 vs reference).
// ---------------------------------------------------------------------------
__global__ void __launch_bounds__(256) qk_tc(float* __restrict__ qkout)
{
    const int tid = threadIdx.x;
    const int bh = blockIdx.z;
    const int b = bh >> 4, h = bh & 15;
    const int t0 = blockIdx.y << 7;
    const int s0 = blockIdx.x << 6;

    if (s0 >= t0 + 128) {                  // fully masked tile
        float4 mv = make_float4(-1e9f, -1e9f, -1e9f, -1e9f);
        #pragma unroll
        for (int i = 0; i < 8; i++) {
            int fi = tid + (i << 8);
            int r = fi >> 4, c = (fi & 15) << 2;
            *(float4*)&qkout[((size_t)bh * T_ + t0 + r) * T_ + s0 + c] = mv;
        }
        return;
    }

    __shared__ __align__(16) __nv_bfloat16 sAh[128 * PITCH];
    __shared__ __align__(16) __nv_bfloat16 sAl[128 * PITCH];
    __shared__ __align__(16) __nv_bfloat16 sBh[64 * PITCH];
    __shared__ __align__(16) __nv_bfloat16 sBl[64 * PITCH];

    const int lane = tid & 31;
    const int wid  = tid >> 5;
    const int wm   = (wid & 3) << 5;
    const int wn   = (wid >> 2) << 5;

    const float* Q = g_q + (size_t)b * T_ * D_ + h * HD_;
    const float* K = g_k + (size_t)b * T_ * D_ + h * HD_;

    float acc[2][4][4] = {};

    for (int k0 = 0; k0 < HD_; k0 += 32) {
        #pragma unroll
        for (int i = 0; i < 4; i++) {
            int fi = tid + (i << 8);
            int r = fi >> 3, kq = (fi & 7) << 2;
            float4 v = *(const float4*)&Q[(size_t)(t0 + r) * D_ + k0 + kq];
            float vv[4] = {v.x, v.y, v.z, v.w};
            #pragma unroll
            for (int j = 0; j < 4; j++)
                split_store(&sAh[r * PITCH + kq + j], &sAl[r * PITCH + kq + j], vv[j]);
        }
        #pragma unroll
        for (int i = 0; i < 2; i++) {
            int fi = tid + (i << 8);
            int r = fi >> 3, kq = (fi & 7) << 2;
            float4 v = *(const float4*)&K[(size_t)(s0 + r) * D_ + k0 + kq];
            float vv[4] = {v.x, v.y, v.z, v.w};
            #pragma unroll
            for (int j = 0; j < 4; j++)
                split_store(&sBh[r * PITCH + kq + j], &sBl[r * PITCH + kq + j], vv[j]);
        }
        __syncthreads();

        #pragma unroll
        for (int ks = 0; ks < 32; ks += 16) {
            const int ar = wm + (lane >> 2);
            const int ac = ks + ((lane & 3) << 1);
            uint32_t ah[2][4], al[2][4];
            #pragma unroll
            for (int mt = 0; mt < 2; mt++) {
                int r = ar + (mt << 4);
                ah[mt][0] = lds2(sAh, r, ac);     ah[mt][1] = lds2(sAh, r + 8, ac);
                ah[mt][2] = lds2(sAh, r, ac + 8); ah[mt][3] = lds2(sAh, r + 8, ac + 8);
                al[mt][0] = lds2(sAl, r, ac);     al[mt][1] = lds2(sAl, r + 8, ac);
                al[mt][2] = lds2(sAl, r, ac + 8); al[mt][3] = lds2(sAl, r + 8, ac + 8);
            }
            const int br = wn + (lane >> 2);
            uint32_t bhf[4][2], blf[4][2];
            #pragma unroll
            for (int nt = 0; nt < 4; nt++) {
                int r = br + (nt << 3);
                bhf[nt][0] = lds2(sBh, r, ac); bhf[nt][1] = lds2(sBh, r, ac + 8);
                blf[nt][0] = lds2(sBl, r, ac); blf[nt][1] = lds2(sBl, r, ac + 8);
            }
            #pragma unroll
            for (int mt = 0; mt < 2; mt++)
                #pragma unroll
                for (int nt = 0; nt < 4; nt++) {
                    mma_bf16(acc[mt][nt], ah[mt], bhf[nt]);
                    mma_bf16(acc[mt][nt], ah[mt], blf[nt]);
                    mma_bf16(acc[mt][nt], al[mt], bhf[nt]);
                }
        }
        __syncthreads();
    }

    #pragma unroll
    for (int mt = 0; mt < 2; mt++) {
        int t = t0 + wm + (mt << 4) + (lane >> 2);
        #pragma unroll
        for (int nt = 0; nt < 4; nt++) {
            int s = s0 + wn + (nt << 3) + ((lane & 3) << 1);
            float2 o0, o1;
            o0.x = acc[mt][nt][0] + ((s     > t) ? -1e9f : 0.f);
            o0.y = acc[mt][nt][1] + ((s + 1 > t) ? -1e9f : 0.f);
            o1.x = acc[mt][nt][2] + ((s     > t + 8) ? -1e9f : 0.f);
            o1.y = acc[mt][nt][3] + ((s + 1 > t + 8) ? -1e9f : 0.f);
            *(float2*)&qkout[((size_t)bh * T_ + t) * T_ + s] = o0;
            *(float2*)&qkout[((size_t)bh * T_ + t + 8) * T_ + s] = o1;
        }
    }
}

// ---------------------------------------------------------------------------
// Softmax stats: reads only columns [0, t].
// ---------------------------------------------------------------------------
__global__ void __launch_bounds__(256) softstats_kernel(const float* __restrict__ qk)
{
    __shared__ float red[256];
    const int row = blockIdx.x;
    const int t   = row & (T_ - 1);
    const int nw  = (t >> 2) + 1;
    const int tid = threadIdx.x;
    const float4* p = (const float4*)(qk + (size_t)row * T_);

    float4 v0 = make_float4(-1e30f, -1e30f, -1e30f, -1e30f);
    float4 v1 = v0;
    if (tid < nw)       v0 = p[tid];
    if (tid + 256 < nw) v1 = p[tid + 256];

    float m = fmaxf(fmaxf(fmaxf(v0.x, v0.y), fmaxf(v0.z, v0.w)),
                    fmaxf(fmaxf(v1.x, v1.y), fmaxf(v1.z, v1.w)));
    red[tid] = m;
    __syncthreads();
    for (int s = 128; s > 0; s >>= 1) {
        if (tid < s) red[tid] = fmaxf(red[tid], red[tid + s]);
        __syncthreads();
    }
    m = red[0];
    __syncthreads();

    float sum = fexp(v0.x - m) + fexp(v0.y - m) + fexp(v0.z - m) + fexp(v0.w - m)
              + fexp(v1.x - m) + fexp(v1.y - m) + fexp(v1.z - m) + fexp(v1.w - m);
    red[tid] = sum;
    __syncthreads();
    for (int s = 128; s > 0; s >>= 1) {
        if (tid < s) red[tid] += red[tid + s];
        __syncthreads();
    }
    if (tid == 0) { g_rmax[row] = m; g_rinv[row] = 1.0f / red[0]; }
}

// ---------------------------------------------------------------------------
// wv via tensor cores: 128(t) x 64(hd) tiles, s-loop only over s <= t0+127.
// P split hi/lo at fill (exp applied), V transposed to col-major smem.
// ---------------------------------------------------------------------------
__global__ void __launch_bounds__(256) wv_tc(const float* __restrict__ qk)
{
    __shared__ __align__(16) __nv_bfloat16 sPh[128 * PITCH];
    __shared__ __align__(16) __nv_bfloat16 sPl[128 * PITCH];
    __shared__ __align__(16) __nv_bfloat16 sVh[64 * PITCH];
    __shared__ __align__(16) __nv_bfloat16 sVl[64 * PITCH];
    __shared__ float mrow[128];

    const int tid  = threadIdx.x;
    const int lane = tid & 31;
    const int wid  = tid >> 5;
    const int wm   = (wid & 3) << 5;
    const int wn   = (wid >> 2) << 5;
    const int bh   = blockIdx.y;
    const int b    = bh >> 4, h = bh & 15;
    const int t0   = blockIdx.x << 7;

    if (tid < 128) mrow[tid] = g_rmax[bh * T_ + t0 + tid];
    __syncthreads();

    const float* P = qk + ((size_t)bh * T_ + t0) * T_;
    const float* V = g_v + (size_t)b * T_ * D_ + h * HD_;

    float acc[2][4][4] = {};
    const int send = t0 + 128;

    for (int s0 = 0; s0 < send; s0 += 32) {
        // P tile 128x32 (exp + split)
        #pragma unroll
        for (int i = 0; i < 4; i++) {
            int fi = tid + (i << 8);
            int r = fi >> 3, kq = (fi & 7) << 2;
            float mr = mrow[r];
            float4 v = *(const float4*)&P[(size_t)r * T_ + s0 + kq];
            float e[4] = {fexp(v.x - mr), fexp(v.y - mr), fexp(v.z - mr), fexp(v.w - mr)};
            #pragma unroll
            for (int j = 0; j < 4; j++)
                split_store(&sPh[r * PITCH + kq + j], &sPl[r * PITCH + kq + j], e[j]);
        }
        // V tile 32(s) x 64(hd), transposed: sV[hd][s]
        #pragma unroll
        for (int i = 0; i < 2; i++) {
            int fi = tid + (i << 8);
            int s = fi >> 4, hq = (fi & 15) << 2;
            float4 v = *(const float4*)&V[(size_t)(s0 + s) * D_ + hq];
            float vv[4] = {v.x, v.y, v.z, v.w};
            #pragma unroll
            for (int j = 0; j < 4; j++)
                split_store(&sVh[(hq + j) * PITCH + s], &sVl[(hq + j) * PITCH + s], vv[j]);
        }
        __syncthreads();

        #pragma unroll
        for (int ks = 0; ks < 32; ks += 16) {
            const int ar = wm + (lane >> 2);
            const int ac = ks + ((lane & 3) << 1);
            uint32_t ah[2][4], al[2][4];
            #pragma unroll
            for (int mt = 0; mt < 2; mt++) {
                int r = ar + (mt << 4);
                ah[mt][0] = lds2(sPh, r, ac);     ah[mt][1] = lds2(sPh, r + 8, ac);
                ah[mt][2] = lds2(sPh, r, ac + 8); ah[mt][3] = lds2(sPh, r + 8, ac + 8);
                al[mt][0] = lds2(sPl, r, ac);     al[mt][1] = lds2(sPl, r + 8, ac);
                al[mt][2] = lds2(sPl, r, ac + 8); al[mt][3] = lds2(sPl, r + 8, ac + 8);
            }
            const int br = wn + (lane >> 2);
            uint32_t bhf[4][2], blf[4][2];
            #pragma unroll
            for (int nt = 0; nt < 4; nt++) {
                int r = br + (nt << 3);
                bhf[nt][0] = lds2(sVh, r, ac); bhf[nt][1] = lds2(sVh, r, ac + 8);
                blf[nt][0] = lds2(sVl, r, ac); blf[nt][1] = lds2(sVl, r, ac + 8);
            }
            #pragma unroll
            for (int mt = 0; mt < 2; mt++)
                #pragma unroll
                for (int nt = 0; nt < 4; nt++) {
                    mma_bf16(acc[mt][nt], ah[mt], bhf[nt]);
                    mma_bf16(acc[mt][nt], ah[mt], blf[nt]);
                    mma_bf16(acc[mt][nt], al[mt], bhf[nt]);
                }
        }
        __syncthreads();
    }

    #pragma unroll
    for (int mt = 0; mt < 2; mt++) {
        int m0 = t0 + wm + (mt << 4) + (lane >> 2);
        float ri0 = g_rinv[bh * T_ + m0];
        float ri1 = g_rinv[bh * T_ + m0 + 8];
        #pragma unroll
        for (int nt = 0; nt < 4; nt++) {
            int n0 = wn + (nt << 3) + ((lane & 3) << 1);
            *(float2*)&g_wv[(size_t)(b * T_ + m0) * D_ + h * HD_ + n0] =
                make_float2(acc[mt][nt][0] * ri0, acc[mt][nt][1] * ri0);
            *(float2*)&g_wv[(size_t)(b * T_ + m0 + 8) * D_ + h * HD_ + n0] =
                make_float2(acc[mt][nt][2] * ri1, acc[mt][nt][3] * ri1);
        }
    }
}

// ---------------------------------------------------------------------------
extern "C" void kernel_launch(void* const* d_in, const int* in_sizes, int n_in,
                              void* d_out, int out_size)
{
    const float* x    = (const float*)d_in[0];
    const float* cosp = (const float*)d_in[2];
    const float* sinp = (const float*)d_in[3];
    const float* Wq   = (const float*)d_in[4];
    const float* bq   = (const float*)d_in[5];
    const float* Wk   = (const float*)d_in[6];
    const float* Wv   = (const float*)d_in[7];
    const float* bv   = (const float*)d_in[8];
    const float* Wo   = (const float*)d_in[9];
    const float* bo   = (const float*)d_in[10];

    float* out = (float*)d_out;
    float* qk  = out + (size_t)M_ * D_;

    dim3 gg(D_ / 64, M_ / 128);
    gemm_tc<<<gg, 256>>>(x, Wq, bq, nullptr, 0);
    gemm_tc<<<gg, 256>>>(x, Wk, nullptr, nullptr, 1);
    gemm_tc<<<gg, 256>>>(x, Wv, bv, nullptr, 2);

    rope_kernel<<<M_ * 512 / 256, 256>>>(cosp, sinp, 0);
    rope_kernel<<<M_ * 512 / 256, 256>>>(cosp, sinp, 1);

    dim3 gqk(T_ / 64, T_ / 128, B_ * H_);
    qk_tc<<<gqk, 256>>>(qk);

    softstats_kernel<<<B_ * H_ * T_, 256>>>(qk);

    dim3 gwv(T_ / 128, B_ * H_);
    wv_tc<<<gwv, 256>>>(qk);

    gemm_tc<<<gg, 256>>>(nullptr, Wo, bo, out, 3);
}

// round 4
// speedup vs baseline: 2.2243x; 1.0515x over previous
#include <cuda_runtime.h>
#include <cuda_bf16.h>
#include <cstdint>

#define B_  2
#define T_  2048
#define D_  1024
#define H_  16
#define HD_ 64
#define M_  (B_*T_)   // 4096
#define PITCH 40      // bf16 per smem row: 20 words -> conflict-free frag loads

// fp32 intermediates (pre-rope q/k)
__device__ float g_q[M_*D_];
__device__ float g_k[M_*D_];
// bf16 hi/lo split operands
__device__ __nv_bfloat16 g_xh[M_*D_],  g_xl[M_*D_];
__device__ __nv_bfloat16 g_qh[M_*D_],  g_ql[M_*D_];
__device__ __nv_bfloat16 g_kh[M_*D_],  g_kl[M_*D_];
__device__ __nv_bfloat16 g_vh[M_*D_],  g_vl[M_*D_];
__device__ __nv_bfloat16 g_ah[M_*D_],  g_al[M_*D_];   // wv (attention out)
__device__ __nv_bfloat16 w_qh[D_*D_],  w_ql[D_*D_];
__device__ __nv_bfloat16 w_kh[D_*D_],  w_kl[D_*D_];
__device__ __nv_bfloat16 w_vh[D_*D_],  w_vl[D_*D_];
__device__ __nv_bfloat16 w_oh[D_*D_],  w_ol[D_*D_];
__device__ float g_rmax[B_*H_*T_];
__device__ float g_rinv[B_*H_*T_];

// Fast exp on the FMA pipe.
__device__ __forceinline__ float fexp(float x) {
    float y = fmaxf(x * 1.44269504f, -126.0f);
    float z = y + 12582912.0f;
    int   n = __float_as_int(z) - 0x4B400000;
    float f = y - (z - 12582912.0f);
    float p = 1.3333558e-3f;
    p = fmaf(p, f, 9.6181291e-3f);
    p = fmaf(p, f, 5.5504109e-2f);
    p = fmaf(p, f, 2.4022651e-1f);
    p = fmaf(p, f, 6.9314718e-1f);
    p = fmaf(p, f, 1.0f);
    return p * __int_as_float((n << 23) + 0x3F800000);
}

__device__ __forceinline__ void mma_bf16(float* c, const uint32_t* a, const uint32_t* b) {
    asm volatile(
        "mma.sync.aligned.m16n8k16.row.col.f32.bf16.bf16.f32 "
        "{%0,%1,%2,%3}, {%4,%5,%6,%7}, {%8,%9}, {%0,%1,%2,%3};\n"
        : "+f"(c[0]), "+f"(c[1]), "+f"(c[2]), "+f"(c[3])
        : "r"(a[0]), "r"(a[1]), "r"(a[2]), "r"(a[3]), "r"(b[0]), "r"(b[1]));
}

__device__ __forceinline__ uint32_t lds2(const __nv_bfloat16* p, int r, int c) {
    return *(const uint32_t*)(p + r * PITCH + c);
}

// split a,b (consecutive) into packed-bf16x2 hi and lo words
__device__ __forceinline__ void split2(float a, float b, uint32_t& hi, uint32_t& lo) {
    __nv_bfloat16 ah = __float2bfloat16(a);
    __nv_bfloat16 bh = __float2bfloat16(b);
    __nv_bfloat16 al = __float2bfloat16(a - __bfloat162float(ah));
    __nv_bfloat16 bl = __float2bfloat16(b - __bfloat162float(bh));
    hi = (uint32_t)__bfloat16_as_ushort(ah) | ((uint32_t)__bfloat16_as_ushort(bh) << 16);
    lo = (uint32_t)__bfloat16_as_ushort(al) | ((uint32_t)__bfloat16_as_ushort(bl) << 16);
}

__device__ __forceinline__ void cpa16(void* s, const void* g) {
    uint32_t sa = (uint32_t)__cvta_generic_to_shared(s);
    asm volatile("cp.async.ca.shared.global [%0], [%1], 16;\n" :: "r"(sa), "l"(g));
}

// ---------------------------------------------------------------------------
// fp32 -> bf16 hi/lo, elementwise (x and weights, once per launch)
// ---------------------------------------------------------------------------
__global__ void __launch_bounds__(256) presplit(
    const float* __restrict__ s, __nv_bfloat16* __restrict__ dh,
    __nv_bfloat16* __restrict__ dl, int n4)
{
    int i = blockIdx.x * 256 + threadIdx.x;
    if (i >= n4) return;
    float4 v = ((const float4*)s)[i];
    uint32_t h0, l0, h1, l1;
    split2(v.x, v.y, h0, l0);
    split2(v.z, v.w, h1, l1);
    ((uint2*)dh)[i] = make_uint2(h0, h1);
    ((uint2*)dl)[i] = make_uint2(l0, l1);
}

// ---------------------------------------------------------------------------
// Dense GEMM (NT), pre-split bf16 operands, cp.async double buffer.
// C = A @ W^T + bias.  128x64 tile, k-step 32.
// Cf!=null -> fp32 out; else split-write (Ch, Cl).
// ---------------------------------------------------------------------------
#define STG_ (384*PITCH)   // bf16 elements per stage

__global__ void __launch_bounds__(256) gemm_tc(
    const __nv_bfloat16* __restrict__ Ah, const __nv_bfloat16* __restrict__ Al,
    const __nv_bfloat16* __restrict__ Wh, const __nv_bfloat16* __restrict__ Wl,
    const float* __restrict__ bias, float* __restrict__ Cf,
    __nv_bfloat16* __restrict__ Ch, __nv_bfloat16* __restrict__ Cl)
{
    extern __shared__ __align__(16) __nv_bfloat16 sm[];   // 2 stages
    const int OAh = 0, OAl = 128 * PITCH, OBh = 256 * PITCH, OBl = 320 * PITCH;

    const int tid = threadIdx.x, lane = tid & 31, wid = tid >> 5;
    const int wm = (wid & 3) << 5, wn = (wid >> 2) << 5;
    const int bm = blockIdx.y << 7, bn = blockIdx.x << 6;

    auto prefetch = [&](int kt, int s) {
        int k0 = kt << 5;
        __nv_bfloat16* st = sm + s * STG_;
        #pragma unroll
        for (int i = 0; i < 2; i++) {
            int c = tid + (i << 8);
            int r = c >> 2, cq = (c & 3) << 3;
            cpa16(&st[OAh + r * PITCH + cq], &Ah[(size_t)(bm + r) * D_ + k0 + cq]);
            cpa16(&st[OAl + r * PITCH + cq], &Al[(size_t)(bm + r) * D_ + k0 + cq]);
        }
        {
            int r = tid >> 2, cq = (tid & 3) << 3;
            cpa16(&st[OBh + r * PITCH + cq], &Wh[(size_t)(bn + r) * D_ + k0 + cq]);
            cpa16(&st[OBl + r * PITCH + cq], &Wl[(size_t)(bn + r) * D_ + k0 + cq]);
        }
        asm volatile("cp.async.commit_group;\n");
    };

    float acc[2][4][4] = {};
    prefetch(0, 0);
    int buf = 0;
    const int KT = D_ / 32;

    for (int kt = 0; kt < KT; kt++) {
        if (kt + 1 < KT) {
            prefetch(kt + 1, buf ^ 1);
            asm volatile("cp.async.wait_group 1;\n");
        } else {
            asm volatile("cp.async.wait_group 0;\n");
        }
        __syncthreads();

        const __nv_bfloat16* st = sm + buf * STG_;
        const __nv_bfloat16* sAh = st + OAh;
        const __nv_bfloat16* sAl = st + OAl;
        const __nv_bfloat16* sBh = st + OBh;
        const __nv_bfloat16* sBl = st + OBl;

        #pragma unroll
        for (int ks = 0; ks < 32; ks += 16) {
            const int ar = wm + (lane >> 2);
            const int ac = ks + ((lane & 3) << 1);
            uint32_t ah[2][4], al[2][4];
            #pragma unroll
            for (int mt = 0; mt < 2; mt++) {
                int r = ar + (mt << 4);
                ah[mt][0] = lds2(sAh, r, ac);     ah[mt][1] = lds2(sAh, r + 8, ac);
                ah[mt][2] = lds2(sAh, r, ac + 8); ah[mt][3] = lds2(sAh, r + 8, ac + 8);
                al[mt][0] = lds2(sAl, r, ac);     al[mt][1] = lds2(sAl, r + 8, ac);
                al[mt][2] = lds2(sAl, r, ac + 8); al[mt][3] = lds2(sAl, r + 8, ac + 8);
            }
            const int br = wn + (lane >> 2);
            uint32_t bh[4][2], bl[4][2];
            #pragma unroll
            for (int nt = 0; nt < 4; nt++) {
                int r = br + (nt << 3);
                bh[nt][0] = lds2(sBh, r, ac); bh[nt][1] = lds2(sBh, r, ac + 8);
                bl[nt][0] = lds2(sBl, r, ac); bl[nt][1] = lds2(sBl, r, ac + 8);
            }
            #pragma unroll
            for (int mt = 0; mt < 2; mt++)
                #pragma unroll
                for (int nt = 0; nt < 4; nt++) {
                    mma_bf16(acc[mt][nt], ah[mt], bh[nt]);
                    mma_bf16(acc[mt][nt], ah[mt], bl[nt]);
                    mma_bf16(acc[mt][nt], al[mt], bh[nt]);
                }
        }
        __syncthreads();
        buf ^= 1;
    }

    #pragma unroll
    for (int mt = 0; mt < 2; mt++) {
        int m0 = bm + wm + (mt << 4) + (lane >> 2);
        #pragma unroll
        for (int nt = 0; nt < 4; nt++) {
            int n0 = bn + wn + (nt << 3) + ((lane & 3) << 1);
            float b0 = 0.f, b1 = 0.f;
            if (bias) { b0 = bias[n0]; b1 = bias[n0 + 1]; }
            float v00 = acc[mt][nt][0] + b0, v01 = acc[mt][nt][1] + b1;
            float v10 = acc[mt][nt][2] + b0, v11 = acc[mt][nt][3] + b1;
            if (Cf) {
                *(float2*)&Cf[(size_t)m0 * D_ + n0]       = make_float2(v00, v01);
                *(float2*)&Cf[(size_t)(m0 + 8) * D_ + n0] = make_float2(v10, v11);
            } else {
                uint32_t h, l;
                split2(v00, v01, h, l);
                *(uint32_t*)&Ch[(size_t)m0 * D_ + n0] = h;
                *(uint32_t*)&Cl[(size_t)m0 * D_ + n0] = l;
                split2(v10, v11, h, l);
                *(uint32_t*)&Ch[(size_t)(m0 + 8) * D_ + n0] = h;
                *(uint32_t*)&Cl[(size_t)(m0 + 8) * D_ + n0] = l;
            }
        }
    }
}

// ---------------------------------------------------------------------------
// RoPE + scale, fp32 in -> bf16 hi/lo out.
// ---------------------------------------------------------------------------
__global__ void __launch_bounds__(256) rope_split(
    const float* __restrict__ src, __nv_bfloat16* __restrict__ dh,
    __nv_bfloat16* __restrict__ dl,
    const float* __restrict__ cosp, const float* __restrict__ sinp)
{
    int idx = blockIdx.x * 256 + threadIdx.x;     // M_*512 pairs
    int m = idx >> 9, pr = idx & 511;
    int t = m & (T_ - 1);
    int p = pr & 31;
    float c = cosp[t * 32 + p], s = sinp[t * 32 + p];
    float2 ab = *(const float2*)(src + (size_t)m * D_ + pr * 2);
    const float scale = 0.35355339059327373f;
    float ox = (ab.x * c - ab.y * s) * scale;
    float oy = (ab.x * s + ab.y * c) * scale;
    uint32_t h, l;
    split2(ox, oy, h, l);
    ((uint32_t*)dh)[(size_t)m * (D_ / 2) + pr] = h;
    ((uint32_t*)dl)[(size_t)m * (D_ / 2) + pr] = l;
}

// ---------------------------------------------------------------------------
// qk via tensor cores, bf16 pre-split inputs. 128(t) x 64(s), K=64.
// ---------------------------------------------------------------------------
__global__ void __launch_bounds__(256) qk_tc(float* __restrict__ qkout)
{
    const int tid = threadIdx.x;
    const int bh = blockIdx.z;
    const int b = bh >> 4, h = bh & 15;
    const int t0 = blockIdx.y << 7;
    const int s0 = blockIdx.x << 6;

    if (s0 >= t0 + 128) {                  // fully masked tile
        float4 mv = make_float4(-1e9f, -1e9f, -1e9f, -1e9f);
        #pragma unroll
        for (int i = 0; i < 8; i++) {
            int fi = tid + (i << 8);
            int r = fi >> 4, c = (fi & 15) << 2;
            *(float4*)&qkout[((size_t)bh * T_ + t0 + r) * T_ + s0 + c] = mv;
        }
        return;
    }

    __shared__ __align__(16) __nv_bfloat16 sQh[128 * PITCH];
    __shared__ __align__(16) __nv_bfloat16 sQl[128 * PITCH];
    __shared__ __align__(16) __nv_bfloat16 sKh[64 * PITCH];
    __shared__ __align__(16) __nv_bfloat16 sKl[64 * PITCH];

    const int lane = tid & 31;
    const int wid  = tid >> 5;
    const int wm   = (wid & 3) << 5;
    const int wn   = (wid >> 2) << 5;

    const __nv_bfloat16* Qh = g_qh + (size_t)b * T_ * D_ + h * HD_;
    const __nv_bfloat16* Ql = g_ql + (size_t)b * T_ * D_ + h * HD_;
    const __nv_bfloat16* Kh = g_kh + (size_t)b * T_ * D_ + h * HD_;
    const __nv_bfloat16* Kl = g_kl + (size_t)b * T_ * D_ + h * HD_;

    float acc[2][4][4] = {};

    for (int k0 = 0; k0 < HD_; k0 += 32) {
        #pragma unroll
        for (int i = 0; i < 2; i++) {
            int c = tid + (i << 8);
            int r = c >> 2, cq = (c & 3) << 3;
            *(uint4*)&sQh[r * PITCH + cq] = *(const uint4*)&Qh[(size_t)(t0 + r) * D_ + k0 + cq];
            *(uint4*)&sQl[r * PITCH + cq] = *(const uint4*)&Ql[(size_t)(t0 + r) * D_ + k0 + cq];
        }
        {
            int r = tid >> 2, cq = (tid & 3) << 3;
            *(uint4*)&sKh[r * PITCH + cq] = *(const uint4*)&Kh[(size_t)(s0 + r) * D_ + k0 + cq];
            *(uint4*)&sKl[r * PITCH + cq] = *(const uint4*)&Kl[(size_t)(s0 + r) * D_ + k0 + cq];
        }
        __syncthreads();

        #pragma unroll
        for (int ks = 0; ks < 32; ks += 16) {
            const int ar = wm + (lane >> 2);
            const int ac = ks + ((lane & 3) << 1);
            uint32_t ah[2][4], al[2][4];
            #pragma unroll
            for (int mt = 0; mt < 2; mt++) {
                int r = ar + (mt << 4);
                ah[mt][0] = lds2(sQh, r, ac);     ah[mt][1] = lds2(sQh, r + 8, ac);
                ah[mt][2] = lds2(sQh, r, ac + 8); ah[mt][3] = lds2(sQh, r + 8, ac + 8);
                al[mt][0] = lds2(sQl, r, ac);     al[mt][1] = lds2(sQl, r + 8, ac);
                al[mt][2] = lds2(sQl, r, ac + 8); al[mt][3] = lds2(sQl, r + 8, ac + 8);
            }
            const int br = wn + (lane >> 2);
            uint32_t bhf[4][2], blf[4][2];
            #pragma unroll
            for (int nt = 0; nt < 4; nt++) {
                int r = br + (nt << 3);
                bhf[nt][0] = lds2(sKh, r, ac); bhf[nt][1] = lds2(sKh, r, ac + 8);
                blf[nt][0] = lds2(sKl, r, ac); blf[nt][1] = lds2(sKl, r, ac + 8);
            }
            #pragma unroll
            for (int mt = 0; mt < 2; mt++)
                #pragma unroll
                for (int nt = 0; nt < 4; nt++) {
                    mma_bf16(acc[mt][nt], ah[mt], bhf[nt]);
                    mma_bf16(acc[mt][nt], ah[mt], blf[nt]);
                    mma_bf16(acc[mt][nt], al[mt], bhf[nt]);
                }
        }
        __syncthreads();
    }

    #pragma unroll
    for (int mt = 0; mt < 2; mt++) {
        int t = t0 + wm + (mt << 4) + (lane >> 2);
        #pragma unroll
        for (int nt = 0; nt < 4; nt++) {
            int s = s0 + wn + (nt << 3) + ((lane & 3) << 1);
            float2 o0, o1;
            o0.x = acc[mt][nt][0] + ((s     > t) ? -1e9f : 0.f);
            o0.y = acc[mt][nt][1] + ((s + 1 > t) ? -1e9f : 0.f);
            o1.x = acc[mt][nt][2] + ((s     > t + 8) ? -1e9f : 0.f);
            o1.y = acc[mt][nt][3] + ((s + 1 > t + 8) ? -1e9f : 0.f);
            *(float2*)&qkout[((size_t)bh * T_ + t) * T_ + s] = o0;
            *(float2*)&qkout[((size_t)bh * T_ + t + 8) * T_ + s] = o1;
        }
    }
}

// ---------------------------------------------------------------------------
// Softmax stats: reads only columns [0, t].
// ---------------------------------------------------------------------------
__global__ void __launch_bounds__(256) softstats_kernel(const float* __restrict__ qk)
{
    __shared__ float red[256];
    const int row = blockIdx.x;
    const int t   = row & (T_ - 1);
    const int nw  = (t >> 2) + 1;
    const int tid = threadIdx.x;
    const float4* p = (const float4*)(qk + (size_t)row * T_);

    float4 v0 = make_float4(-1e30f, -1e30f, -1e30f, -1e30f);
    float4 v1 = v0;
    if (tid < nw)       v0 = p[tid];
    if (tid + 256 < nw) v1 = p[tid + 256];

    float m = fmaxf(fmaxf(fmaxf(v0.x, v0.y), fmaxf(v0.z, v0.w)),
                    fmaxf(fmaxf(v1.x, v1.y), fmaxf(v1.z, v1.w)));
    red[tid] = m;
    __syncthreads();
    for (int s = 128; s > 0; s >>= 1) {
        if (tid < s) red[tid] = fmaxf(red[tid], red[tid + s]);
        __syncthreads();
    }
    m = red[0];
    __syncthreads();

    float sum = fexp(v0.x - m) + fexp(v0.y - m) + fexp(v0.z - m) + fexp(v0.w - m)
              + fexp(v1.x - m) + fexp(v1.y - m) + fexp(v1.z - m) + fexp(v1.w - m);
    red[tid] = sum;
    __syncthreads();
    for (int s = 128; s > 0; s >>= 1) {
        if (tid < s) red[tid] += red[tid + s];
        __syncthreads();
    }
    if (tid == 0) { g_rmax[row] = m; g_rinv[row] = 1.0f / red[0]; }
}

// ---------------------------------------------------------------------------
// wv via tensor cores: P = exp(qk - max), split at fill; V pre-split bf16,
// transposed at fill. Causal: s <= t0+127 only. Split-writes wv (g_ah/g_al).
// ---------------------------------------------------------------------------
__global__ void __launch_bounds__(256) wv_tc(const float* __restrict__ qk)
{
    __shared__ __align__(16) __nv_bfloat16 sPh[128 * PITCH];
    __shared__ __align__(16) __nv_bfloat16 sPl[128 * PITCH];
    __shared__ __align__(16) __nv_bfloat16 sVh[64 * PITCH];
    __shared__ __align__(16) __nv_bfloat16 sVl[64 * PITCH];
    __shared__ float mrow[128];

    const int tid  = threadIdx.x;
    const int lane = tid & 31;
    const int wid  = tid >> 5;
    const int wm   = (wid & 3) << 5;
    const int wn   = (wid >> 2) << 5;
    const int bh   = blockIdx.y;
    const int b    = bh >> 4, h = bh & 15;
    const int t0   = blockIdx.x << 7;

    if (tid < 128) mrow[tid] = g_rmax[bh * T_ + t0 + tid];
    __syncthreads();

    const float* P = qk + ((size_t)bh * T_ + t0) * T_;
    const __nv_bfloat16* Vh = g_vh + (size_t)b * T_ * D_ + h * HD_;
    const __nv_bfloat16* Vl = g_vl + (size_t)b * T_ * D_ + h * HD_;

    float acc[2][4][4] = {};
    const int send = t0 + 128;

    for (int s0 = 0; s0 < send; s0 += 32) {
        #pragma unroll
        for (int i = 0; i < 4; i++) {
            int fi = tid + (i << 8);
            int r = fi >> 3, kq = (fi & 7) << 2;
            float mr = mrow[r];
            float4 v = *(const float4*)&P[(size_t)r * T_ + s0 + kq];
            uint32_t h0, l0, h1, l1;
            split2(fexp(v.x - mr), fexp(v.y - mr), h0, l0);
            split2(fexp(v.z - mr), fexp(v.w - mr), h1, l1);
            *(uint2*)&sPh[r * PITCH + kq] = make_uint2(h0, h1);
            *(uint2*)&sPl[r * PITCH + kq] = make_uint2(l0, l1);
        }
        #pragma unroll
        for (int i = 0; i < 2; i++) {
            int fi = tid + (i << 8);
            int s = fi >> 4, hq = (fi & 15) << 2;
            uint2 vh = *(const uint2*)&Vh[(size_t)(s0 + s) * D_ + hq];
            uint2 vl = *(const uint2*)&Vl[(size_t)(s0 + s) * D_ + hq];
            const __nv_bfloat16* ph = (const __nv_bfloat16*)&vh;
            const __nv_bfloat16* pl = (const __nv_bfloat16*)&vl;
            #pragma unroll
            for (int j = 0; j < 4; j++) {
                sVh[(hq + j) * PITCH + s] = ph[j];
                sVl[(hq + j) * PITCH + s] = pl[j];
            }
        }
        __syncthreads();

        #pragma unroll
        for (int ks = 0; ks < 32; ks += 16) {
            const int ar = wm + (lane >> 2);
            const int ac = ks + ((lane & 3) << 1);
            uint32_t ah[2][4], al[2][4];
            #pragma unroll
            for (int mt = 0; mt < 2; mt++) {
                int r = ar + (mt << 4);
                ah[mt][0] = lds2(sPh, r, ac);     ah[mt][1] = lds2(sPh, r + 8, ac);
                ah[mt][2] = lds2(sPh, r, ac + 8); ah[mt][3] = lds2(sPh, r + 8, ac + 8);
                al[mt][0] = lds2(sPl, r, ac);     al[mt][1] = lds2(sPl, r + 8, ac);
                al[mt][2] = lds2(sPl, r, ac + 8); al[mt][3] = lds2(sPl, r + 8, ac + 8);
            }
            const int br = wn + (lane >> 2);
            uint32_t bhf[4][2], blf[4][2];
            #pragma unroll
            for (int nt = 0; nt < 4; nt++) {
                int r = br + (nt << 3);
                bhf[nt][0] = lds2(sVh, r, ac); bhf[nt][1] = lds2(sVh, r, ac + 8);
                blf[nt][0] = lds2(sVl, r, ac); blf[nt][1] = lds2(sVl, r, ac + 8);
            }
            #pragma unroll
            for (int mt = 0; mt < 2; mt++)
                #pragma unroll
                for (int nt = 0; nt < 4; nt++) {
                    mma_bf16(acc[mt][nt], ah[mt], bhf[nt]);
                    mma_bf16(acc[mt][nt], ah[mt], blf[nt]);
                    mma_bf16(acc[mt][nt], al[mt], bhf[nt]);
                }
        }
        __syncthreads();
    }

    #pragma unroll
    for (int mt = 0; mt < 2; mt++) {
        int m0 = t0 + wm + (mt << 4) + (lane >> 2);
        float ri0 = g_rinv[bh * T_ + m0];
        float ri1 = g_rinv[bh * T_ + m0 + 8];
        #pragma unroll
        for (int nt = 0; nt < 4; nt++) {
            int n0 = wn + (nt << 3) + ((lane & 3) << 1);
            size_t o0 = (size_t)(b * T_ + m0) * D_ + h * HD_ + n0;
            size_t o1 = (size_t)(b * T_ + m0 + 8) * D_ + h * HD_ + n0;
            uint32_t hh, ll;
            split2(acc[mt][nt][0] * ri0, acc[mt][nt][1] * ri0, hh, ll);
            *(uint32_t*)&g_ah[o0] = hh; *(uint32_t*)&g_al[o0] = ll;
            split2(acc[mt][nt][2] * ri1, acc[mt][nt][3] * ri1, hh, ll);
            *(uint32_t*)&g_ah[o1] = hh; *(uint32_t*)&g_al[o1] = ll;
        }
    }
}

// ---------------------------------------------------------------------------
extern "C" void kernel_launch(void* const* d_in, const int* in_sizes, int n_in,
                              void* d_out, int out_size)
{
    const float* x    = (const float*)d_in[0];
    const float* cosp = (const float*)d_in[2];
    const float* sinp = (const float*)d_in[3];
    const float* Wq   = (const float*)d_in[4];
    const float* bq   = (const float*)d_in[5];
    const float* Wk   = (const float*)d_in[6];
    const float* Wv   = (const float*)d_in[7];
    const float* bv   = (const float*)d_in[8];
    const float* Wo   = (const float*)d_in[9];
    const float* bo   = (const float*)d_in[10];

    float* out = (float*)d_out;
    float* qk  = out + (size_t)M_ * D_;

    static bool attr_done = false;
    if (!attr_done) {
        cudaFuncSetAttribute(gemm_tc, cudaFuncAttributeMaxDynamicSharedMemorySize,
                             2 * STG_ * (int)sizeof(__nv_bfloat16));
        attr_done = true;
    }
    const int gsm = 2 * STG_ * (int)sizeof(__nv_bfloat16);   // 61440

    __nv_bfloat16 *xh, *xl, *qh_, *ql_, *kh_, *kl_, *vh_, *vl_, *ah_, *al_;
    __nv_bfloat16 *wqh, *wql, *wkh, *wkl, *wvh, *wvl, *woh, *wol;
    float *gq, *gk;
    cudaGetSymbolAddress((void**)&xh,  g_xh); cudaGetSymbolAddress((void**)&xl,  g_xl);
    cudaGetSymbolAddress((void**)&qh_, g_qh); cudaGetSymbolAddress((void**)&ql_, g_ql);
    cudaGetSymbolAddress((void**)&kh_, g_kh); cudaGetSymbolAddress((void**)&kl_, g_kl);
    cudaGetSymbolAddress((void**)&vh_, g_vh); cudaGetSymbolAddress((void**)&vl_, g_vl);
    cudaGetSymbolAddress((void**)&ah_, g_ah); cudaGetSymbolAddress((void**)&al_, g_al);
    cudaGetSymbolAddress((void**)&wqh, w_qh); cudaGetSymbolAddress((void**)&wql, w_ql);
    cudaGetSymbolAddress((void**)&wkh, w_kh); cudaGetSymbolAddress((void**)&wkl, w_kl);
    cudaGetSymbolAddress((void**)&wvh, w_vh); cudaGetSymbolAddress((void**)&wvl, w_vl);
    cudaGetSymbolAddress((void**)&woh, w_oh); cudaGetSymbolAddress((void**)&wol, w_ol);
    cudaGetSymbolAddress((void**)&gq,  g_q);  cudaGetSymbolAddress((void**)&gk,  g_k);

    // pre-split x and weights
    presplit<<<(M_*D_/4 + 255)/256, 256>>>(x,  xh,  xl,  M_*D_/4);
    presplit<<<(D_*D_/4 + 255)/256, 256>>>(Wq, wqh, wql, D_*D_/4);
    presplit<<<(D_*D_/4 + 255)/256, 256>>>(Wk, wkh, wkl, D_*D_/4);
    presplit<<<(D_*D_/4 + 255)/256, 256>>>(Wv, wvh, wvl, D_*D_/4);
    presplit<<<(D_*D_/4 + 255)/256, 256>>>(Wo, woh, wol, D_*D_/4);

    dim3 gg(D_ / 64, M_ / 128);
    gemm_tc<<<gg, 256, gsm>>>(xh, xl, wqh, wql, bq,      gq,   nullptr, nullptr);
    gemm_tc<<<gg, 256, gsm>>>(xh, xl, wkh, wkl, nullptr, gk,   nullptr, nullptr);
    gemm_tc<<<gg, 256, gsm>>>(xh, xl, wvh, wvl, bv,      nullptr, vh_, vl_);

    rope_split<<<M_ * 512 / 256, 256>>>(gq, qh_, ql_, cosp, sinp);
    rope_split<<<M_ * 512 / 256, 256>>>(gk, kh_, kl_, cosp, sinp);

    dim3 gqk(T_ / 64, T_ / 128, B_ * H_);
    qk_tc<<<gqk, 256>>>(qk);

    softstats_kernel<<<B_ * H_ * T_, 256>>>(qk);

    dim3 gwv(T_ / 128, B_ * H_);
    wv_tc<<<gwv, 256>>>(qk);

    gemm_tc<<<gg, 256, gsm>>>(ah_, al_, woh, wol, bo, out, nullptr, nullptr);
}

// round 7
// speedup vs baseline: 2.3720x; 1.0664x over previous
#include <cuda_runtime.h>
#include <cuda_bf16.h>
#include <cstdint>

#define B_  2
#define T_  2048
#define D_  1024
#define H_  16
#define HD_ 64
#define M_  (B_*T_)   // 4096
#define PITCH 40      // bf16 per smem row: 80B, conflict-free for LDSM

// fp32 intermediates (pre-rope q/k)
__device__ float g_q[M_*D_];
__device__ float g_k[M_*D_];
// bf16 hi/lo split operands
__device__ __nv_bfloat16 g_xh[M_*D_],  g_xl[M_*D_];
__device__ __nv_bfloat16 g_qh[M_*D_],  g_ql[M_*D_];
__device__ __nv_bfloat16 g_kh[M_*D_],  g_kl[M_*D_];
__device__ __nv_bfloat16 g_vh[M_*D_],  g_vl[M_*D_];
__device__ __nv_bfloat16 g_ah[M_*D_],  g_al[M_*D_];   // wv (attention out)
__device__ __nv_bfloat16 w_qh[D_*D_],  w_ql[D_*D_];
__device__ __nv_bfloat16 w_kh[D_*D_],  w_kl[D_*D_];
__device__ __nv_bfloat16 w_vh[D_*D_],  w_vl[D_*D_];
__device__ __nv_bfloat16 w_oh[D_*D_],  w_ol[D_*D_];
__device__ float g_rmax[B_*H_*T_];
__device__ float g_rinv[B_*H_*T_];

// Fast exp on the FMA pipe.
__device__ __forceinline__ float fexp(float x) {
    float y = fmaxf(x * 1.44269504f, -126.0f);
    float z = y + 12582912.0f;
    int   n = __float_as_int(z) - 0x4B400000;
    float f = y - (z - 12582912.0f);
    float p = 1.3333558e-3f;
    p = fmaf(p, f, 9.6181291e-3f);
    p = fmaf(p, f, 5.5504109e-2f);
    p = fmaf(p, f, 2.4022651e-1f);
    p = fmaf(p, f, 6.9314718e-1f);
    p = fmaf(p, f, 1.0f);
    return p * __int_as_float((n << 23) + 0x3F800000);
}

__device__ __forceinline__ void mma_bf16(float* c, const uint32_t* a, const uint32_t* b) {
    asm volatile(
        "mma.sync.aligned.m16n8k16.row.col.f32.bf16.bf16.f32 "
        "{%0,%1,%2,%3}, {%4,%5,%6,%7}, {%8,%9}, {%0,%1,%2,%3};\n"
        : "+f"(c[0]), "+f"(c[1]), "+f"(c[2]), "+f"(c[3])
        : "r"(a[0]), "r"(a[1]), "r"(a[2]), "r"(a[3]), "r"(b[0]), "r"(b[1]));
}

// ldmatrix x4: 4 8x8 bf16 tiles -> 4 regs; thread t supplies row (t&7) of tile (t>>3)
__device__ __forceinline__ void ldsm_x4(uint32_t& r0, uint32_t& r1, uint32_t& r2,
                                        uint32_t& r3, uint32_t addr) {
    asm volatile("ldmatrix.sync.aligned.m8n8.x4.shared.b16 {%0,%1,%2,%3}, [%4];"
                 : "=r"(r0), "=r"(r1), "=r"(r2), "=r"(r3) : "r"(addr));
}

__device__ __forceinline__ uint32_t smem_u32(const void* p) {
    return (uint32_t)__cvta_generic_to_shared(p);
}

// split a,b (consecutive) into packed-bf16x2 hi and lo words
__device__ __forceinline__ void split2(float a, float b, uint32_t& hi, uint32_t& lo) {
    __nv_bfloat16 ah = __float2bfloat16(a);
    __nv_bfloat16 bh = __float2bfloat16(b);
    __nv_bfloat16 al = __float2bfloat16(a - __bfloat162float(ah));
    __nv_bfloat16 bl = __float2bfloat16(b - __bfloat162float(bh));
    hi = (uint32_t)__bfloat16_as_ushort(ah) | ((uint32_t)__bfloat16_as_ushort(bh) << 16);
    lo = (uint32_t)__bfloat16_as_ushort(al) | ((uint32_t)__bfloat16_as_ushort(bl) << 16);
}

__device__ __forceinline__ void cpa16(void* s, const void* g) {
    uint32_t sa = (uint32_t)__cvta_generic_to_shared(s);
    asm volatile("cp.async.ca.shared.global [%0], [%1], 16;\n" :: "r"(sa), "l"(g));
}

// ---------------------------------------------------------------------------
// presplit: fp32 -> bf16 hi/lo, elementwise
// ---------------------------------------------------------------------------
__global__ void __launch_bounds__(256) presplit(
    const float* __restrict__ s, __nv_bfloat16* __restrict__ dh,
    __nv_bfloat16* __restrict__ dl, int n4)
{
    int i = blockIdx.x * 256 + threadIdx.x;
    if (i >= n4) return;
    float4 v = ((const float4*)s)[i];
    uint32_t h0, l0, h1, l1;
    split2(v.x, v.y, h0, l0);
    split2(v.z, v.w, h1, l1);
    ((uint2*)dh)[i] = make_uint2(h0, h1);
    ((uint2*)dl)[i] = make_uint2(l0, l1);
}

// ---------------------------------------------------------------------------
// Dense GEMM (NT), pre-split bf16, cp.async double buffer, LDSM frag loads.
// C = A @ W^T + bias.  128x64 tile, k-step 32.
// ---------------------------------------------------------------------------
#define STG_ (384*PITCH)   // bf16 elements per stage
#define STGB (STG_*2)      // bytes per stage (30720)
#define OAlB (128*PITCH*2) // 10240
#define OBhB (256*PITCH*2) // 20480
#define OBlB (320*PITCH*2) // 25600

__global__ void __launch_bounds__(256) gemm_tc(
    const __nv_bfloat16* __restrict__ Ah, const __nv_bfloat16* __restrict__ Al,
    const __nv_bfloat16* __restrict__ Wh, const __nv_bfloat16* __restrict__ Wl,
    const float* __restrict__ bias, float* __restrict__ Cf,
    __nv_bfloat16* __restrict__ Ch, __nv_bfloat16* __restrict__ Cl)
{
    extern __shared__ __align__(16) __nv_bfloat16 sm[];   // 2 stages

    const int tid = threadIdx.x, lane = tid & 31, wid = tid >> 5;
    const int wm = (wid & 3) << 5, wn = (wid >> 2) << 5;
    const int bm = blockIdx.y << 7, bn = blockIdx.x << 6;
    const int m8 = lane >> 3, r8 = lane & 7;
    const uint32_t smb = smem_u32(sm);

    // per-thread LDSM byte offsets within a stage
    const uint32_t aoff0 = ((uint32_t)((wm + r8 + ((m8 & 1) << 3)) * PITCH
                                       + ((m8 >> 1) << 3))) * 2;
    const uint32_t boff0 = ((uint32_t)((wn + r8 + ((m8 >> 1) << 3)) * PITCH
                                       + ((m8 & 1) << 3))) * 2;

    auto prefetch = [&](int kt, int s) {
        int k0 = kt << 5;
        __nv_bfloat16* st = sm + s * STG_;
        #pragma unroll
        for (int i = 0; i < 2; i++) {
            int c = tid + (i << 8);
            int r = c >> 2, cq = (c & 3) << 3;
            cpa16(&st[r * PITCH + cq],               &Ah[(size_t)(bm + r) * D_ + k0 + cq]);
            cpa16(&st[128 * PITCH + r * PITCH + cq], &Al[(size_t)(bm + r) * D_ + k0 + cq]);
        }
        {
            int r = tid >> 2, cq = (tid & 3) << 3;
            cpa16(&st[256 * PITCH + r * PITCH + cq], &Wh[(size_t)(bn + r) * D_ + k0 + cq]);
            cpa16(&st[320 * PITCH + r * PITCH + cq], &Wl[(size_t)(bn + r) * D_ + k0 + cq]);
        }
        asm volatile("cp.async.commit_group;\n");
    };

    float acc[2][4][4] = {};
    prefetch(0, 0);
    int buf = 0;
    const int KT = D_ / 32;

    for (int kt = 0; kt < KT; kt++) {
        if (kt + 1 < KT) {
            prefetch(kt + 1, buf ^ 1);
            asm volatile("cp.async.wait_group 1;\n");
        } else {
            asm volatile("cp.async.wait_group 0;\n");
        }
        __syncthreads();

        const uint32_t stb = smb + buf * STGB;
        #pragma unroll
        for (int ks = 0; ks < 32; ks += 16) {
            const uint32_t ka = ks * 2;   // byte advance for k offset
            uint32_t ah[2][4], al[2][4], bh[4][2], bl[4][2];
            ldsm_x4(ah[0][0], ah[0][1], ah[0][2], ah[0][3], stb + aoff0 + ka);
            ldsm_x4(ah[1][0], ah[1][1], ah[1][2], ah[1][3], stb + aoff0 + ka + 16 * PITCH * 2);
            ldsm_x4(al[0][0], al[0][1], al[0][2], al[0][3], stb + OAlB + aoff0 + ka);
            ldsm_x4(al[1][0], al[1][1], al[1][2], al[1][3], stb + OAlB + aoff0 + ka + 16 * PITCH * 2);
            ldsm_x4(bh[0][0], bh[0][1], bh[1][0], bh[1][1], stb + OBhB + boff0 + ka);
            ldsm_x4(bh[2][0], bh[2][1], bh[3][0], bh[3][1], stb + OBhB + boff0 + ka + 16 * PITCH * 2);
            ldsm_x4(bl[0][0], bl[0][1], bl[1][0], bl[1][1], stb + OBlB + boff0 + ka);
            ldsm_x4(bl[2][0], bl[2][1], bl[3][0], bl[3][1], stb + OBlB + boff0 + ka + 16 * PITCH * 2);
            #pragma unroll
            for (int mt = 0; mt < 2; mt++)
                #pragma unroll
                for (int nt = 0; nt < 4; nt++) {
                    mma_bf16(acc[mt][nt], ah[mt], bh[nt]);
                    mma_bf16(acc[mt][nt], ah[mt], bl[nt]);
                    mma_bf16(acc[mt][nt], al[mt], bh[nt]);
                }
        }
        __syncthreads();
        buf ^= 1;
    }

    #pragma unroll
    for (int mt = 0; mt < 2; mt++) {
        int m0 = bm + wm + (mt << 4) + (lane >> 2);
        #pragma unroll
        for (int nt = 0; nt < 4; nt++) {
            int n0 = bn + wn + (nt << 3) + ((lane & 3) << 1);
            float b0 = 0.f, b1 = 0.f;
            if (bias) { b0 = bias[n0]; b1 = bias[n0 + 1]; }
            float v00 = acc[mt][nt][0] + b0, v01 = acc[mt][nt][1] + b1;
            float v10 = acc[mt][nt][2] + b0, v11 = acc[mt][nt][3] + b1;
            if (Cf) {
                *(float2*)&Cf[(size_t)m0 * D_ + n0]       = make_float2(v00, v01);
                *(float2*)&Cf[(size_t)(m0 + 8) * D_ + n0] = make_float2(v10, v11);
            } else {
                uint32_t h, l;
                split2(v00, v01, h, l);
                *(uint32_t*)&Ch[(size_t)m0 * D_ + n0] = h;
                *(uint32_t*)&Cl[(size_t)m0 * D_ + n0] = l;
                split2(v10, v11, h, l);
                *(uint32_t*)&Ch[(size_t)(m0 + 8) * D_ + n0] = h;
                *(uint32_t*)&Cl[(size_t)(m0 + 8) * D_ + n0] = l;
            }
        }
    }
}

// ---------------------------------------------------------------------------
// RoPE + scale, fp32 in -> bf16 hi/lo out.
// ---------------------------------------------------------------------------
__global__ void __launch_bounds__(256) rope_split(
    const float* __restrict__ src, __nv_bfloat16* __restrict__ dh,
    __nv_bfloat16* __restrict__ dl,
    const float* __restrict__ cosp, const float* __restrict__ sinp)
{
    int idx = blockIdx.x * 256 + threadIdx.x;     // M_*512 pairs
    int m = idx >> 9, pr = idx & 511;
    int t = m & (T_ - 1);
    int p = pr & 31;
    float c = cosp[t * 32 + p], s = sinp[t * 32 + p];
    float2 ab = *(const float2*)(src + (size_t)m * D_ + pr * 2);
    const float scale = 0.35355339059327373f;
    float ox = (ab.x * c - ab.y * s) * scale;
    float oy = (ab.x * s + ab.y * c) * scale;
    uint32_t h, l;
    split2(ox, oy, h, l);
    ((uint32_t*)dh)[(size_t)m * (D_ / 2) + pr] = h;
    ((uint32_t*)dl)[(size_t)m * (D_ / 2) + pr] = l;
}

// ---------------------------------------------------------------------------
// qk via mma.sync + LDSM: 128(t) x 64(s), K=64, bf16 pre-split.
// ---------------------------------------------------------------------------
__global__ void __launch_bounds__(256) qk_tc(float* __restrict__ qkout)
{
    const int tid = threadIdx.x;
    const int bh = blockIdx.z;
    const int b = bh >> 4, h = bh & 15;
    const int t0 = blockIdx.y << 7;
    const int s0 = blockIdx.x << 6;

    if (s0 >= t0 + 128) {                  // fully masked tile
        float4 mv = make_float4(-1e9f, -1e9f, -1e9f, -1e9f);
        #pragma unroll
        for (int i = 0; i < 8; i++) {
            int fi = tid + (i << 8);
            int r = fi >> 4, c = (fi & 15) << 2;
            *(float4*)&qkout[((size_t)bh * T_ + t0 + r) * T_ + s0 + c] = mv;
        }
        return;
    }

    __shared__ __align__(16) __nv_bfloat16 sQh[128 * PITCH];
    __shared__ __align__(16) __nv_bfloat16 sQl[128 * PITCH];
    __shared__ __align__(16) __nv_bfloat16 sKh[64 * PITCH];
    __shared__ __align__(16) __nv_bfloat16 sKl[64 * PITCH];

    const int lane = tid & 31;
    const int wid  = tid >> 5;
    const int wm   = (wid & 3) << 5;
    const int wn   = (wid >> 2) << 5;
    const int m8 = lane >> 3, r8 = lane & 7;

    const uint32_t bQh = smem_u32(sQh), bQl = smem_u32(sQl);
    const uint32_t bKh = smem_u32(sKh), bKl = smem_u32(sKl);
    const uint32_t aoff0 = ((uint32_t)((wm + r8 + ((m8 & 1) << 3)) * PITCH
                                       + ((m8 >> 1) << 3))) * 2;
    const uint32_t boff0 = ((uint32_t)((wn + r8 + ((m8 >> 1) << 3)) * PITCH
                                       + ((m8 & 1) << 3))) * 2;

    const __nv_bfloat16* Qh = g_qh + (size_t)b * T_ * D_ + h * HD_;
    const __nv_bfloat16* Ql = g_ql + (size_t)b * T_ * D_ + h * HD_;
    const __nv_bfloat16* Kh = g_kh + (size_t)b * T_ * D_ + h * HD_;
    const __nv_bfloat16* Kl = g_kl + (size_t)b * T_ * D_ + h * HD_;

    float acc[2][4][4] = {};

    for (int k0 = 0; k0 < HD_; k0 += 32) {
        #pragma unroll
        for (int i = 0; i < 2; i++) {
            int c = tid + (i << 8);
            int r = c >> 2, cq = (c & 3) << 3;
            *(uint4*)&sQh[r * PITCH + cq] = *(const uint4*)&Qh[(size_t)(t0 + r) * D_ + k0 + cq];
            *(uint4*)&sQl[r * PITCH + cq] = *(const uint4*)&Ql[(size_t)(t0 + r) * D_ + k0 + cq];
        }
        {
            int r = tid >> 2, cq = (tid & 3) << 3;
            *(uint4*)&sKh[r * PITCH + cq] = *(const uint4*)&Kh[(size_t)(s0 + r) * D_ + k0 + cq];
            *(uint4*)&sKl[r * PITCH + cq] = *(const uint4*)&Kl[(size_t)(s0 + r) * D_ + k0 + cq];
        }
        __syncthreads();

        #pragma unroll
        for (int ks = 0; ks < 32; ks += 16) {
            const uint32_t ka = ks * 2;
            uint32_t ah[2][4], al[2][4], bhf[4][2], blf[4][2];
            ldsm_x4(ah[0][0], ah[0][1], ah[0][2], ah[0][3], bQh + aoff0 + ka);
            ldsm_x4(ah[1][0], ah[1][1], ah[1][2], ah[1][3], bQh + aoff0 + ka + 16 * PITCH * 2);
            ldsm_x4(al[0][0], al[0][1], al[0][2], al[0][3], bQl + aoff0 + ka);
            ldsm_x4(al[1][0], al[1][1], al[1][2], al[1][3], bQl + aoff0 + ka + 16 * PITCH * 2);
            ldsm_x4(bhf[0][0], bhf[0][1], bhf[1][0], bhf[1][1], bKh + boff0 + ka);
            ldsm_x4(bhf[2][0], bhf[2][1], bhf[3][0], bhf[3][1], bKh + boff0 + ka + 16 * PITCH * 2);
            ldsm_x4(blf[0][0], blf[0][1], blf[1][0], blf[1][1], bKl + boff0 + ka);
            ldsm_x4(blf[2][0], blf[2][1], blf[3][0], blf[3][1], bKl + boff0 + ka + 16 * PITCH * 2);
            #pragma unroll
            for (int mt = 0; mt < 2; mt++)
                #pragma unroll
                for (int nt = 0; nt < 4; nt++) {
                    mma_bf16(acc[mt][nt], ah[mt], bhf[nt]);
                    mma_bf16(acc[mt][nt], ah[mt], blf[nt]);
                    mma_bf16(acc[mt][nt], al[mt], bhf[nt]);
                }
        }
        __syncthreads();
    }

    #pragma unroll
    for (int mt = 0; mt < 2; mt++) {
        int t = t0 + wm + (mt << 4) + (lane >> 2);
        #pragma unroll
        for (int nt = 0; nt < 4; nt++) {
            int s = s0 + wn + (nt << 3) + ((lane & 3) << 1);
            float2 o0, o1;
            o0.x = acc[mt][nt][0] + ((s     > t) ? -1e9f : 0.f);
            o0.y = acc[mt][nt][1] + ((s + 1 > t) ? -1e9f : 0.f);
            o1.x = acc[mt][nt][2] + ((s     > t + 8) ? -1e9f : 0.f);
            o1.y = acc[mt][nt][3] + ((s + 1 > t + 8) ? -1e9f : 0.f);
            *(float2*)&qkout[((size_t)bh * T_ + t) * T_ + s] = o0;
            *(float2*)&qkout[((size_t)bh * T_ + t + 8) * T_ + s] = o1;
        }
    }
}

// ---------------------------------------------------------------------------
// Softmax stats: reads only columns [0, t].
// ---------------------------------------------------------------------------
__global__ void __launch_bounds__(256) softstats_kernel(const float* __restrict__ qk)
{
    __shared__ float red[256];
    const int row = blockIdx.x;
    const int t   = row & (T_ - 1);
    const int nw  = (t >> 2) + 1;
    const int tid = threadIdx.x;
    const float4* p = (const float4*)(qk + (size_t)row * T_);

    float4 v0 = make_float4(-1e30f, -1e30f, -1e30f, -1e30f);
    float4 v1 = v0;
    if (tid < nw)       v0 = p[tid];
    if (tid + 256 < nw) v1 = p[tid + 256];

    float m = fmaxf(fmaxf(fmaxf(v0.x, v0.y), fmaxf(v0.z, v0.w)),
                    fmaxf(fmaxf(v1.x, v1.y), fmaxf(v1.z, v1.w)));
    red[tid] = m;
    __syncthreads();
    for (int s = 128; s > 0; s >>= 1) {
        if (tid < s) red[tid] = fmaxf(red[tid], red[tid + s]);
        __syncthreads();
    }
    m = red[0];
    __syncthreads();

    float sum = fexp(v0.x - m) + fexp(v0.y - m) + fexp(v0.z - m) + fexp(v0.w - m)
              + fexp(v1.x - m) + fexp(v1.y - m) + fexp(v1.z - m) + fexp(v1.w - m);
    red[tid] = sum;
    __syncthreads();
    for (int s = 128; s > 0; s >>= 1) {
        if (tid < s) red[tid] += red[tid + s];
        __syncthreads();
    }
    if (tid == 0) { g_rmax[row] = m; g_rinv[row] = 1.0f / red[0]; }
}

// ---------------------------------------------------------------------------
// wv via mma.sync + LDSM: P = exp(qk - max) split at fill; V pre-split,
// transposed at fill. Causal: s <= t0+127. Split-writes wv (g_ah/g_al).
// ---------------------------------------------------------------------------
__global__ void __launch_bounds__(256) wv_tc(const float* __restrict__ qk)
{
    __shared__ __align__(16) __nv_bfloat16 sPh[128 * PITCH];
    __shared__ __align__(16) __nv_bfloat16 sPl[128 * PITCH];
    __shared__ __align__(16) __nv_bfloat16 sVh[64 * PITCH];
    __shared__ __align__(16) __nv_bfloat16 sVl[64 * PITCH];
    __shared__ float mrow[128];

    const int tid  = threadIdx.x;
    const int lane = tid & 31;
    const int wid  = tid >> 5;
    const int wm   = (wid & 3) << 5;
    const int wn   = (wid >> 2) << 5;
    const int bh   = blockIdx.y;
    const int b    = bh >> 4, h = bh & 15;
    const int t0   = blockIdx.x << 7;
    const int m8 = lane >> 3, r8 = lane & 7;

    const uint32_t bPh = smem_u32(sPh), bPl = smem_u32(sPl);
    const uint32_t bVh = smem_u32(sVh), bVl = smem_u32(sVl);
    const uint32_t aoff0 = ((uint32_t)((wm + r8 + ((m8 & 1) << 3)) * PITCH
                                       + ((m8 >> 1) << 3))) * 2;
    const uint32_t boff0 = ((uint32_t)((wn + r8 + ((m8 >> 1) << 3)) * PITCH
                                       + ((m8 & 1) << 3))) * 2;

    if (tid < 128) mrow[tid] = g_rmax[bh * T_ + t0 + tid];
    __syncthreads();

    const float* P = qk + ((size_t)bh * T_ + t0) * T_;
    const __nv_bfloat16* Vh = g_vh + (size_t)b * T_ * D_ + h * HD_;
    const __nv_bfloat16* Vl = g_vl + (size_t)b * T_ * D_ + h * HD_;

    float acc[2][4][4] = {};
    const int send = t0 + 128;

    for (int s0 = 0; s0 < send; s0 += 32) {
        #pragma unroll
        for (int i = 0; i < 4; i++) {
            int fi = tid + (i << 8);
            int r = fi >> 3, kq = (fi & 7) << 2;
            float mr = mrow[r];
            float4 v = *(const float4*)&P[(size_t)r * T_ + s0 + kq];
            uint32_t h0, l0, h1, l1;
            split2(fexp(v.x - mr), fexp(v.y - mr), h0, l0);
            split2(fexp(v.z - mr), fexp(v.w - mr), h1, l1);
            *(uint2*)&sPh[r * PITCH + kq] = make_uint2(h0, h1);
            *(uint2*)&sPl[r * PITCH + kq] = make_uint2(l0, l1);
        }
        #pragma unroll
        for (int i = 0; i < 2; i++) {
            int fi = tid + (i << 8);
            int s = fi >> 4, hq = (fi & 15) << 2;
            uint2 vh = *(const uint2*)&Vh[(size_t)(s0 + s) * D_ + hq];
            uint2 vl = *(const uint2*)&Vl[(size_t)(s0 + s) * D_ + hq];
            const __nv_bfloat16* ph = (const __nv_bfloat16*)&vh;
            const __nv_bfloat16* pl = (const __nv_bfloat16*)&vl;
            #pragma unroll
            for (int j = 0; j < 4; j++) {
                sVh[(hq + j) * PITCH + s] = ph[j];
                sVl[(hq + j) * PITCH + s] = pl[j];
            }
        }
        __syncthreads();

        #pragma unroll
        for (int ks = 0; ks < 32; ks += 16) {
            const uint32_t ka = ks * 2;
            uint32_t ah[2][4], al[2][4], bhf[4][2], blf[4][2];
            ldsm_x4(ah[0][0], ah[0][1], ah[0][2], ah[0][3], bPh + aoff0 + ka);
            ldsm_x4(ah[1][0], ah[1][1], ah[1][2], ah[1][3], bPh + aoff0 + ka + 16 * PITCH * 2);
            ldsm_x4(al[0][0], al[0][1], al[0][2], al[0][3], bPl + aoff0 + ka);
            ldsm_x4(al[1][0], al[1][1], al[1][2], al[1][3], bPl + aoff0 + ka + 16 * PITCH * 2);
            ldsm_x4(bhf[0][0], bhf[0][1], bhf[1][0], bhf[1][1], bVh + boff0 + ka);
            ldsm_x4(bhf[2][0], bhf[2][1], bhf[3][0], bhf[3][1], bVh + boff0 + ka + 16 * PITCH * 2);
            ldsm_x4(blf[0][0], blf[0][1], blf[1][0], blf[1][1], bVl + boff0 + ka);
            ldsm_x4(blf[2][0], blf[2][1], blf[3][0], blf[3][1], bVl + boff0 + ka + 16 * PITCH * 2);
            #pragma unroll
            for (int mt = 0; mt < 2; mt++)
                #pragma unroll
                for (int nt = 0; nt < 4; nt++) {
                    mma_bf16(acc[mt][nt], ah[mt], bhf[nt]);
                    mma_bf16(acc[mt][nt], ah[mt], blf[nt]);
                    mma_bf16(acc[mt][nt], al[mt], bhf[nt]);
                }
        }
        __syncthreads();
    }

    #pragma unroll
    for (int mt = 0; mt < 2; mt++) {
        int m0 = t0 + wm + (mt << 4) + (lane >> 2);
        float ri0 = g_rinv[bh * T_ + m0];
        float ri1 = g_rinv[bh * T_ + m0 + 8];
        #pragma unroll
        for (int nt = 0; nt < 4; nt++) {
            int n0 = wn + (nt << 3) + ((lane & 3) << 1);
            size_t o0 = (size_t)(b * T_ + m0) * D_ + h * HD_ + n0;
            size_t o1 = (size_t)(b * T_ + m0 + 8) * D_ + h * HD_ + n0;
            uint32_t hh, ll;
            split2(acc[mt][nt][0] * ri0, acc[mt][nt][1] * ri0, hh, ll);
            *(uint32_t*)&g_ah[o0] = hh; *(uint32_t*)&g_al[o0] = ll;
            split2(acc[mt][nt][2] * ri1, acc[mt][nt][3] * ri1, hh, ll);
            *(uint32_t*)&g_ah[o1] = hh; *(uint32_t*)&g_al[o1] = ll;
        }
    }
}

// ---------------------------------------------------------------------------
extern "C" void kernel_launch(void* const* d_in, const int* in_sizes, int n_in,
                              void* d_out, int out_size)
{
    const float* x    = (const float*)d_in[0];
    const float* cosp = (const float*)d_in[2];
    const float* sinp = (const float*)d_in[3];
    const float* Wq   = (const float*)d_in[4];
    const float* bq   = (const float*)d_in[5];
    const float* Wk   = (const float*)d_in[6];
    const float* Wv   = (const float*)d_in[7];
    const float* bv   = (const float*)d_in[8];
    const float* Wo   = (const float*)d_in[9];
    const float* bo   = (const float*)d_in[10];

    float* out = (float*)d_out;
    float* qk  = out + (size_t)M_ * D_;

    static bool attr_done = false;
    if (!attr_done) {
        cudaFuncSetAttribute(gemm_tc, cudaFuncAttributeMaxDynamicSharedMemorySize,
                             2 * STGB);
        attr_done = true;
    }
    const int gsm = 2 * STGB;   // 61440

    __nv_bfloat16 *xh, *xl, *qh_, *ql_, *kh_, *kl_, *vh_, *vl_, *ah_, *al_;
    __nv_bfloat16 *wqh, *wql, *wkh, *wkl, *wvh, *wvl, *woh, *wol;
    float *gq, *gk;
    cudaGetSymbolAddress((void**)&xh,  g_xh); cudaGetSymbolAddress((void**)&xl,  g_xl);
    cudaGetSymbolAddress((void**)&qh_, g_qh); cudaGetSymbolAddress((void**)&ql_, g_ql);
    cudaGetSymbolAddress((void**)&kh_, g_kh); cudaGetSymbolAddress((void**)&kl_, g_kl);
    cudaGetSymbolAddress((void**)&vh_, g_vh); cudaGetSymbolAddress((void**)&vl_, g_vl);
    cudaGetSymbolAddress((void**)&ah_, g_ah); cudaGetSymbolAddress((void**)&al_, g_al);
    cudaGetSymbolAddress((void**)&wqh, w_qh); cudaGetSymbolAddress((void**)&wql, w_ql);
    cudaGetSymbolAddress((void**)&wkh, w_kh); cudaGetSymbolAddress((void**)&wkl, w_kl);
    cudaGetSymbolAddress((void**)&wvh, w_vh); cudaGetSymbolAddress((void**)&wvl, w_vl);
    cudaGetSymbolAddress((void**)&woh, w_oh); cudaGetSymbolAddress((void**)&wol, w_ol);
    cudaGetSymbolAddress((void**)&gq,  g_q);  cudaGetSymbolAddress((void**)&gk,  g_k);

    presplit<<<(M_*D_/4 + 255)/256, 256>>>(x,  xh,  xl,  M_*D_/4);
    presplit<<<(D_*D_/4 + 255)/256, 256>>>(Wq, wqh, wql, D_*D_/4);
    presplit<<<(D_*D_/4 + 255)/256, 256>>>(Wk, wkh, wkl, D_*D_/4);
    presplit<<<(D_*D_/4 + 255)/256, 256>>>(Wv, wvh, wvl, D_*D_/4);
    presplit<<<(D_*D_/4 + 255)/256, 256>>>(Wo, woh, wol, D_*D_/4);

    dim3 gg(D_ / 64, M_ / 128);
    gemm_tc<<<gg, 256, gsm>>>(xh, xl, wqh, wql, bq,      gq,   nullptr, nullptr);
    gemm_tc<<<gg, 256, gsm>>>(xh, xl, wkh, wkl, nullptr, gk,   nullptr, nullptr);
    gemm_tc<<<gg, 256, gsm>>>(xh, xl, wvh, wvl, bv,      nullptr, vh_, vl_);

    rope_split<<<M_ * 512 / 256, 256>>>(gq, qh_, ql_, cosp, sinp);
    rope_split<<<M_ * 512 / 256, 256>>>(gk, kh_, kl_, cosp, sinp);

    dim3 gqk(T_ / 64, T_ / 128, B_ * H_);
    qk_tc<<<gqk, 256>>>(qk);

    softstats_kernel<<<B_ * H_ * T_, 256>>>(qk);

    dim3 gwv(T_ / 128, B_ * H_);
    wv_tc<<<gwv, 256>>>(qk);

    gemm_tc<<<gg, 256, gsm>>>(ah_, al_, woh, wol, bo, out, nullptr, nullptr);
}

// round 8
// speedup vs baseline: 2.7294x; 1.1507x over previous
#include <cuda_runtime.h>
#include <cuda_bf16.h>
#include <cstdint>

#define B_  2
#define T_  2048
#define D_  1024
#define H_  16
#define HD_ 64
#define M_  (B_*T_)   // 4096
#define PITCH 40      // bf16 per smem row: 80B, conflict-free for LDSM

// fp32 intermediates (pre-rope q/k)
__device__ float g_q[M_*D_];
__device__ float g_k[M_*D_];
// bf16 hi/lo split operands
__device__ __nv_bfloat16 g_xh[M_*D_],  g_xl[M_*D_];
__device__ __nv_bfloat16 g_qh[M_*D_],  g_ql[M_*D_];
__device__ __nv_bfloat16 g_kh[M_*D_],  g_kl[M_*D_];
__device__ __nv_bfloat16 g_vh[M_*D_],  g_vl[M_*D_];
__device__ __nv_bfloat16 g_ah[M_*D_],  g_al[M_*D_];   // wv (attention out)
__device__ __nv_bfloat16 w_qh[D_*D_],  w_ql[D_*D_];
__device__ __nv_bfloat16 w_kh[D_*D_],  w_kl[D_*D_];
__device__ __nv_bfloat16 w_vh[D_*D_],  w_vl[D_*D_];
__device__ __nv_bfloat16 w_oh[D_*D_],  w_ol[D_*D_];

// Fast exp on the FMA pipe.
__device__ __forceinline__ float fexp(float x) {
    float y = fmaxf(x * 1.44269504f, -126.0f);
    float z = y + 12582912.0f;
    int   n = __float_as_int(z) - 0x4B400000;
    float f = y - (z - 12582912.0f);
    float p = 1.3333558e-3f;
    p = fmaf(p, f, 9.6181291e-3f);
    p = fmaf(p, f, 5.5504109e-2f);
    p = fmaf(p, f, 2.4022651e-1f);
    p = fmaf(p, f, 6.9314718e-1f);
    p = fmaf(p, f, 1.0f);
    return p * __int_as_float((n << 23) + 0x3F800000);
}

__device__ __forceinline__ void mma_bf16(float* c, const uint32_t* a, const uint32_t* b) {
    asm volatile(
        "mma.sync.aligned.m16n8k16.row.col.f32.bf16.bf16.f32 "
        "{%0,%1,%2,%3}, {%4,%5,%6,%7}, {%8,%9}, {%0,%1,%2,%3};\n"
        : "+f"(c[0]), "+f"(c[1]), "+f"(c[2]), "+f"(c[3])
        : "r"(a[0]), "r"(a[1]), "r"(a[2]), "r"(a[3]), "r"(b[0]), "r"(b[1]));
}

__device__ __forceinline__ void ldsm_x4(uint32_t& r0, uint32_t& r1, uint32_t& r2,
                                        uint32_t& r3, uint32_t addr) {
    asm volatile("ldmatrix.sync.aligned.m8n8.x4.shared.b16 {%0,%1,%2,%3}, [%4];"
                 : "=r"(r0), "=r"(r1), "=r"(r2), "=r"(r3) : "r"(addr));
}

__device__ __forceinline__ uint32_t smem_u32(const void* p) {
    return (uint32_t)__cvta_generic_to_shared(p);
}

__device__ __forceinline__ void split2(float a, float b, uint32_t& hi, uint32_t& lo) {
    __nv_bfloat16 ah = __float2bfloat16(a);
    __nv_bfloat16 bh = __float2bfloat16(b);
    __nv_bfloat16 al = __float2bfloat16(a - __bfloat162float(ah));
    __nv_bfloat16 bl = __float2bfloat16(b - __bfloat162float(bh));
    hi = (uint32_t)__bfloat16_as_ushort(ah) | ((uint32_t)__bfloat16_as_ushort(bh) << 16);
    lo = (uint32_t)__bfloat16_as_ushort(al) | ((uint32_t)__bfloat16_as_ushort(bl) << 16);
}

__device__ __forceinline__ void cpa16(void* s, const void* g) {
    uint32_t sa = (uint32_t)__cvta_generic_to_shared(s);
    asm volatile("cp.async.ca.shared.global [%0], [%1], 16;\n" :: "r"(sa), "l"(g));
}

// ---------------------------------------------------------------------------
// presplit: fp32 -> bf16 hi/lo, elementwise
// ---------------------------------------------------------------------------
__global__ void __launch_bounds__(256) presplit(
    const float* __restrict__ s, __nv_bfloat16* __restrict__ dh,
    __nv_bfloat16* __restrict__ dl, int n4)
{
    int i = blockIdx.x * 256 + threadIdx.x;
    if (i >= n4) return;
    float4 v = ((const float4*)s)[i];
    uint32_t h0, l0, h1, l1;
    split2(v.x, v.y, h0, l0);
    split2(v.z, v.w, h1, l1);
    ((uint2*)dh)[i] = make_uint2(h0, h1);
    ((uint2*)dl)[i] = make_uint2(l0, l1);
}

// ---------------------------------------------------------------------------
// Dense GEMM (NT), pre-split bf16, cp.async double buffer, LDSM frag loads.
// ---------------------------------------------------------------------------
#define STG_ (384*PITCH)
#define STGB (STG_*2)
#define OAlB (128*PITCH*2)
#define OBhB (256*PITCH*2)
#define OBlB (320*PITCH*2)

__global__ void __launch_bounds__(256) gemm_tc(
    const __nv_bfloat16* __restrict__ Ah, const __nv_bfloat16* __restrict__ Al,
    const __nv_bfloat16* __restrict__ Wh, const __nv_bfloat16* __restrict__ Wl,
    const float* __restrict__ bias, float* __restrict__ Cf,
    __nv_bfloat16* __restrict__ Ch, __nv_bfloat16* __restrict__ Cl)
{
    extern __shared__ __align__(16) __nv_bfloat16 sm[];

    const int tid = threadIdx.x, lane = tid & 31, wid = tid >> 5;
    const int wm = (wid & 3) << 5, wn = (wid >> 2) << 5;
    const int bm = blockIdx.y << 7, bn = blockIdx.x << 6;
    const int m8 = lane >> 3, r8 = lane & 7;
    const uint32_t smb = smem_u32(sm);

    const uint32_t aoff0 = ((uint32_t)((wm + r8 + ((m8 & 1) << 3)) * PITCH
                                       + ((m8 >> 1) << 3))) * 2;
    const uint32_t boff0 = ((uint32_t)((wn + r8 + ((m8 >> 1) << 3)) * PITCH
                                       + ((m8 & 1) << 3))) * 2;

    auto prefetch = [&](int kt, int s) {
        int k0 = kt << 5;
        __nv_bfloat16* st = sm + s * STG_;
        #pragma unroll
        for (int i = 0; i < 2; i++) {
            int c = tid + (i << 8);
            int r = c >> 2, cq = (c & 3) << 3;
            cpa16(&st[r * PITCH + cq],               &Ah[(size_t)(bm + r) * D_ + k0 + cq]);
            cpa16(&st[128 * PITCH + r * PITCH + cq], &Al[(size_t)(bm + r) * D_ + k0 + cq]);
        }
        {
            int r = tid >> 2, cq = (tid & 3) << 3;
            cpa16(&st[256 * PITCH + r * PITCH + cq], &Wh[(size_t)(bn + r) * D_ + k0 + cq]);
            cpa16(&st[320 * PITCH + r * PITCH + cq], &Wl[(size_t)(bn + r) * D_ + k0 + cq]);
        }
        asm volatile("cp.async.commit_group;\n");
    };

    float acc[2][4][4] = {};
    prefetch(0, 0);
    int buf = 0;
    const int KT = D_ / 32;

    for (int kt = 0; kt < KT; kt++) {
        if (kt + 1 < KT) {
            prefetch(kt + 1, buf ^ 1);
            asm volatile("cp.async.wait_group 1;\n");
        } else {
            asm volatile("cp.async.wait_group 0;\n");
        }
        __syncthreads();

        const uint32_t stb = smb + buf * STGB;
        #pragma unroll
        for (int ks = 0; ks < 32; ks += 16) {
            const uint32_t ka = ks * 2;
            uint32_t ah[2][4], al[2][4], bh[4][2], bl[4][2];
            ldsm_x4(ah[0][0], ah[0][1], ah[0][2], ah[0][3], stb + aoff0 + ka);
            ldsm_x4(ah[1][0], ah[1][1], ah[1][2], ah[1][3], stb + aoff0 + ka + 16 * PITCH * 2);
            ldsm_x4(al[0][0], al[0][1], al[0][2], al[0][3], stb + OAlB + aoff0 + ka);
            ldsm_x4(al[1][0], al[1][1], al[1][2], al[1][3], stb + OAlB + aoff0 + ka + 16 * PITCH * 2);
            ldsm_x4(bh[0][0], bh[0][1], bh[1][0], bh[1][1], stb + OBhB + boff0 + ka);
            ldsm_x4(bh[2][0], bh[2][1], bh[3][0], bh[3][1], stb + OBhB + boff0 + ka + 16 * PITCH * 2);
            ldsm_x4(bl[0][0], bl[0][1], bl[1][0], bl[1][1], stb + OBlB + boff0 + ka);
            ldsm_x4(bl[2][0], bl[2][1], bl[3][0], bl[3][1], stb + OBlB + boff0 + ka + 16 * PITCH * 2);
            #pragma unroll
            for (int mt = 0; mt < 2; mt++)
                #pragma unroll
                for (int nt = 0; nt < 4; nt++) {
                    mma_bf16(acc[mt][nt], ah[mt], bh[nt]);
                    mma_bf16(acc[mt][nt], ah[mt], bl[nt]);
                    mma_bf16(acc[mt][nt], al[mt], bh[nt]);
                }
        }
        __syncthreads();
        buf ^= 1;
    }

    #pragma unroll
    for (int mt = 0; mt < 2; mt++) {
        int m0 = bm + wm + (mt << 4) + (lane >> 2);
        #pragma unroll
        for (int nt = 0; nt < 4; nt++) {
            int n0 = bn + wn + (nt << 3) + ((lane & 3) << 1);
            float b0 = 0.f, b1 = 0.f;
            if (bias) { b0 = bias[n0]; b1 = bias[n0 + 1]; }
            float v00 = acc[mt][nt][0] + b0, v01 = acc[mt][nt][1] + b1;
            float v10 = acc[mt][nt][2] + b0, v11 = acc[mt][nt][3] + b1;
            if (Cf) {
                *(float2*)&Cf[(size_t)m0 * D_ + n0]       = make_float2(v00, v01);
                *(float2*)&Cf[(size_t)(m0 + 8) * D_ + n0] = make_float2(v10, v11);
            } else {
                uint32_t h, l;
                split2(v00, v01, h, l);
                *(uint32_t*)&Ch[(size_t)m0 * D_ + n0] = h;
                *(uint32_t*)&Cl[(size_t)m0 * D_ + n0] = l;
                split2(v10, v11, h, l);
                *(uint32_t*)&Ch[(size_t)(m0 + 8) * D_ + n0] = h;
                *(uint32_t*)&Cl[(size_t)(m0 + 8) * D_ + n0] = l;
            }
        }
    }
}

// ---------------------------------------------------------------------------
// RoPE + scale, fp32 in -> bf16 hi/lo out.
// ---------------------------------------------------------------------------
__global__ void __launch_bounds__(256) rope_split(
    const float* __restrict__ src, __nv_bfloat16* __restrict__ dh,
    __nv_bfloat16* __restrict__ dl,
    const float* __restrict__ cosp, const float* __restrict__ sinp)
{
    int idx = blockIdx.x * 256 + threadIdx.x;
    int m = idx >> 9, pr = idx & 511;
    int t = m & (T_ - 1);
    int p = pr & 31;
    float c = cosp[t * 32 + p], s = sinp[t * 32 + p];
    float2 ab = *(const float2*)(src + (size_t)m * D_ + pr * 2);
    const float scale = 0.35355339059327373f;
    float ox = (ab.x * c - ab.y * s) * scale;
    float oy = (ab.x * s + ab.y * c) * scale;
    uint32_t h, l;
    split2(ox, oy, h, l);
    ((uint32_t*)dh)[(size_t)m * (D_ / 2) + pr] = h;
    ((uint32_t*)dl)[(size_t)m * (D_ / 2) + pr] = l;
}

// ---------------------------------------------------------------------------
// Fused attention: qk (+store) + online softmax + P@V, one CTA per
// (bh, 128-row t-block). s-tiles of 32. bf16x3 MMA throughout.
// Dynamic smem layout (bf16 elems):
//   Qh[2ch*5120]@0  Ql@10240  Kh[2ch*1280]@20480  Kl@23040
//   Ph[5120]@25600  Pl@30720  Vh[2560]@35840  Vl@38400   (40960 total = 80KB)
// ---------------------------------------------------------------------------
#define ATT_SMEM (40960 * 2)

__global__ void __launch_bounds__(256) att_fused(float* __restrict__ qkout)
{
    extern __shared__ __align__(16) __nv_bfloat16 dsm[];
    __shared__ float mrow[128], frow[128], rsum[128];
    __shared__ float tmax[2][128], tsum[2][128];

    const int tid  = threadIdx.x;
    const int lane = tid & 31;
    const int wid  = tid >> 5;
    const int wm   = (wid & 3) << 5;        // t rows of warp
    const int wh   = wid >> 2;              // warp half (0/1)
    const int wnq  = wh << 4;               // qk s-cols (16-wide)
    const int wnv  = wh << 5;               // wv hd-cols (32-wide)
    const int bh   = blockIdx.y;
    const int b    = bh >> 4, h = bh & 15;
    const int t0   = blockIdx.x << 7;
    const int m8 = lane >> 3, r8 = lane & 7;

    const uint32_t smb = smem_u32(dsm);
    // byte bases
    const uint32_t bQh = smb, bQl = smb + 20480;
    const uint32_t bKh = smb + 40960, bKl = smb + 46080;
    const uint32_t bPh = smb + 51200, bPl = smb + 61440;
    const uint32_t bVh = smb + 71680, bVl = smb + 76800;

    // LDSM per-thread offsets (bytes)
    const uint32_t aoff = ((uint32_t)((wm + r8 + ((m8 & 1) << 3)) * PITCH
                                      + ((m8 >> 1) << 3))) * 2;
    const uint32_t kboff = ((uint32_t)((wnq + r8 + ((m8 >> 1) << 3)) * PITCH
                                       + ((m8 & 1) << 3))) * 2;
    const uint32_t vboff = ((uint32_t)((wnv + r8 + ((m8 >> 1) << 3)) * PITCH
                                       + ((m8 & 1) << 3))) * 2;

    const __nv_bfloat16* Qh = g_qh + (size_t)b * T_ * D_ + h * HD_;
    const __nv_bfloat16* Ql = g_ql + (size_t)b * T_ * D_ + h * HD_;
    const __nv_bfloat16* Kh = g_kh + (size_t)b * T_ * D_ + h * HD_;
    const __nv_bfloat16* Kl = g_kl + (size_t)b * T_ * D_ + h * HD_;
    const __nv_bfloat16* Vh = g_vh + (size_t)b * T_ * D_ + h * HD_;
    const __nv_bfloat16* Vl = g_vl + (size_t)b * T_ * D_ + h * HD_;

    // Q tile fill (128x64 hi/lo), chunked by 32 k-cols
    #pragma unroll
    for (int i = 0; i < 4; i++) {
        int idx = tid + (i << 8);
        int r = idx >> 3, c8 = idx & 7;
        int col = c8 << 3, ch = col >> 5, cc = col & 31;
        int de = ch * 5120 + r * PITCH + cc;
        *(uint4*)&dsm[de]         = *(const uint4*)&Qh[(size_t)(t0 + r) * D_ + col];
        *(uint4*)&dsm[10240 + de] = *(const uint4*)&Ql[(size_t)(t0 + r) * D_ + col];
    }
    if (tid < 128) { mrow[tid] = -1e30f; rsum[tid] = 0.f; }
    __syncthreads();

    float aw[2][4][4] = {};            // P@V accumulators
    const int send = t0 + 128;

    for (int s0 = 0; s0 < send; s0 += 32) {
        // ---- fill K (32x64) and V (32s x 64hd, transposed) ----
        {
            int r = tid >> 3, c8 = tid & 7;
            int col = c8 << 3, ch = col >> 5, cc = col & 31;
            int de = 20480 + ch * 1280 + r * PITCH + cc;
            *(uint4*)&dsm[de]        = *(const uint4*)&Kh[(size_t)(s0 + r) * D_ + col];
            *(uint4*)&dsm[2560 + de] = *(const uint4*)&Kl[(size_t)(s0 + r) * D_ + col];
        }
        #pragma unroll
        for (int i = 0; i < 2; i++) {
            int fi = tid + (i << 8);
            int s = fi >> 4, hq = (fi & 15) << 2;
            uint2 vh = *(const uint2*)&Vh[(size_t)(s0 + s) * D_ + hq];
            uint2 vl = *(const uint2*)&Vl[(size_t)(s0 + s) * D_ + hq];
            const __nv_bfloat16* ph = (const __nv_bfloat16*)&vh;
            const __nv_bfloat16* pl = (const __nv_bfloat16*)&vl;
            #pragma unroll
            for (int j = 0; j < 4; j++) {
                dsm[35840 + (hq + j) * PITCH + s] = ph[j];
                dsm[38400 + (hq + j) * PITCH + s] = pl[j];
            }
        }
        __syncthreads();

        // ---- qk MMA: 128x32 tile, K=64 ----
        float aq[2][2][4] = {};
        #pragma unroll
        for (int c = 0; c < 2; c++) {
            const uint32_t qh_b = bQh + c * 10240, ql_b = bQl + c * 10240;
            const uint32_t kh_b = bKh + c * 2560,  kl_b = bKl + c * 2560;
            #pragma unroll
            for (int ks = 0; ks < 32; ks += 16) {
                const uint32_t ka = ks * 2;
                uint32_t ah[2][4], al[2][4], kh2[2][2], kl2[2][2];
                ldsm_x4(ah[0][0], ah[0][1], ah[0][2], ah[0][3], qh_b + aoff + ka);
                ldsm_x4(ah[1][0], ah[1][1], ah[1][2], ah[1][3], qh_b + aoff + ka + 1280);
                ldsm_x4(al[0][0], al[0][1], al[0][2], al[0][3], ql_b + aoff + ka);
                ldsm_x4(al[1][0], al[1][1], al[1][2], al[1][3], ql_b + aoff + ka + 1280);
                ldsm_x4(kh2[0][0], kh2[0][1], kh2[1][0], kh2[1][1], kh_b + kboff + ka);
                ldsm_x4(kl2[0][0], kl2[0][1], kl2[1][0], kl2[1][1], kl_b + kboff + ka);
                #pragma unroll
                for (int mt = 0; mt < 2; mt++)
                    #pragma unroll
                    for (int nt = 0; nt < 2; nt++) {
                        mma_bf16(aq[mt][nt], ah[mt], kh2[nt]);
                        mma_bf16(aq[mt][nt], ah[mt], kl2[nt]);
                        mma_bf16(aq[mt][nt], al[mt], kh2[nt]);
                    }
            }
        }

        // ---- mask + store + tile row max ----
        float rmx[4] = {-1e30f, -1e30f, -1e30f, -1e30f};
        #pragma unroll
        for (int mt = 0; mt < 2; mt++) {
            int r0 = wm + (mt << 4) + (lane >> 2);       // local rows
            int t_a = t0 + r0, t_b = t_a + 8;
            #pragma unroll
            for (int nt = 0; nt < 2; nt++) {
                int sg = s0 + wnq + (nt << 3) + ((lane & 3) << 1);
                float v0 = aq[mt][nt][0] + ((sg     > t_a) ? -1e9f : 0.f);
                float v1 = aq[mt][nt][1] + ((sg + 1 > t_a) ? -1e9f : 0.f);
                float v2 = aq[mt][nt][2] + ((sg     > t_b) ? -1e9f : 0.f);
                float v3 = aq[mt][nt][3] + ((sg + 1 > t_b) ? -1e9f : 0.f);
                aq[mt][nt][0] = v0; aq[mt][nt][1] = v1;
                aq[mt][nt][2] = v2; aq[mt][nt][3] = v3;
                *(float2*)&qkout[((size_t)bh * T_ + t_a) * T_ + sg] = make_float2(v0, v1);
                *(float2*)&qkout[((size_t)bh * T_ + t_b) * T_ + sg] = make_float2(v2, v3);
                rmx[mt * 2]     = fmaxf(rmx[mt * 2],     fmaxf(v0, v1));
                rmx[mt * 2 + 1] = fmaxf(rmx[mt * 2 + 1], fmaxf(v2, v3));
            }
        }
        #pragma unroll
        for (int k = 1; k < 4; k <<= 1) {
            #pragma unroll
            for (int i = 0; i < 4; i++)
                rmx[i] = fmaxf(rmx[i], __shfl_xor_sync(0xFFFFFFFF, rmx[i], k));
        }
        if ((lane & 3) == 0) {
            int rr = lane >> 2;
            tmax[wh][wm + rr]      = rmx[0];
            tmax[wh][wm + rr + 8]  = rmx[1];
            tmax[wh][wm + rr + 16] = rmx[2];
            tmax[wh][wm + rr + 24] = rmx[3];
        }
        __syncthreads();
        if (tid < 128) {
            float nm = fmaxf(mrow[tid], fmaxf(tmax[0][tid], tmax[1][tid]));
            float f = fexp(mrow[tid] - nm);
            frow[tid] = f; mrow[tid] = nm; rsum[tid] *= f;
        }
        __syncthreads();

        // ---- P = exp(qk - m), write smem, row sums, rescale aw ----
        float psum[4] = {0.f, 0.f, 0.f, 0.f};
        #pragma unroll
        for (int mt = 0; mt < 2; mt++) {
            int r0 = wm + (mt << 4) + (lane >> 2);
            float m0 = mrow[r0], m1 = mrow[r0 + 8];
            #pragma unroll
            for (int nt = 0; nt < 2; nt++) {
                float p0 = fexp(aq[mt][nt][0] - m0);
                float p1 = fexp(aq[mt][nt][1] - m0);
                float p2 = fexp(aq[mt][nt][2] - m1);
                float p3 = fexp(aq[mt][nt][3] - m1);
                psum[mt * 2]     += p0 + p1;
                psum[mt * 2 + 1] += p2 + p3;
                uint32_t hh, ll;
                int colb = (wnq + (nt << 3) + ((lane & 3) << 1)) * 2;
                split2(p0, p1, hh, ll);
                *(uint32_t*)((char*)dsm + (bPh - smb) + r0 * (PITCH * 2) + colb) = hh;
                *(uint32_t*)((char*)dsm + (bPl - smb) + r0 * (PITCH * 2) + colb) = ll;
                split2(p2, p3, hh, ll);
                *(uint32_t*)((char*)dsm + (bPh - smb) + (r0 + 8) * (PITCH * 2) + colb) = hh;
                *(uint32_t*)((char*)dsm + (bPl - smb) + (r0 + 8) * (PITCH * 2) + colb) = ll;
            }
        }
        #pragma unroll
        for (int k = 1; k < 4; k <<= 1) {
            #pragma unroll
            for (int i = 0; i < 4; i++)
                psum[i] += __shfl_xor_sync(0xFFFFFFFF, psum[i], k);
        }
        if ((lane & 3) == 0) {
            int rr = lane >> 2;
            tsum[wh][wm + rr]      = psum[0];
            tsum[wh][wm + rr + 8]  = psum[1];
            tsum[wh][wm + rr + 16] = psum[2];
            tsum[wh][wm + rr + 24] = psum[3];
        }
        // rescale wv accumulators
        {
            int r0 = wm + (lane >> 2);
            float f00 = frow[r0],      f01 = frow[r0 + 8];
            float f10 = frow[r0 + 16], f11 = frow[r0 + 24];
            #pragma unroll
            for (int nt = 0; nt < 4; nt++) {
                aw[0][nt][0] *= f00; aw[0][nt][1] *= f00;
                aw[0][nt][2] *= f01; aw[0][nt][3] *= f01;
                aw[1][nt][0] *= f10; aw[1][nt][1] *= f10;
                aw[1][nt][2] *= f11; aw[1][nt][3] *= f11;
            }
        }
        __syncthreads();
        if (tid < 128) rsum[tid] += tsum[0][tid] + tsum[1][tid];

        // ---- wv MMA: aw += P(128x32) @ V(32x64) ----
        #pragma unroll
        for (int ks = 0; ks < 32; ks += 16) {
            const uint32_t ka = ks * 2;
            uint32_t ph_[2][4], pl_[2][4], vh_[4][2], vl_[4][2];
            ldsm_x4(ph_[0][0], ph_[0][1], ph_[0][2], ph_[0][3], bPh + aoff + ka);
            ldsm_x4(ph_[1][0], ph_[1][1], ph_[1][2], ph_[1][3], bPh + aoff + ka + 1280);
            ldsm_x4(pl_[0][0], pl_[0][1], pl_[0][2], pl_[0][3], bPl + aoff + ka);
            ldsm_x4(pl_[1][0], pl_[1][1], pl_[1][2], pl_[1][3], bPl + aoff + ka + 1280);
            ldsm_x4(vh_[0][0], vh_[0][1], vh_[1][0], vh_[1][1], bVh + vboff + ka);
            ldsm_x4(vh_[2][0], vh_[2][1], vh_[3][0], vh_[3][1], bVh + vboff + ka + 1280);
            ldsm_x4(vl_[0][0], vl_[0][1], vl_[1][0], vl_[1][1], bVl + vboff + ka);
            ldsm_x4(vl_[2][0], vl_[2][1], vl_[3][0], vl_[3][1], bVl + vboff + ka + 1280);
            #pragma unroll
            for (int mt = 0; mt < 2; mt++)
                #pragma unroll
                for (int nt = 0; nt < 4; nt++) {
                    mma_bf16(aw[mt][nt], ph_[mt], vh_[nt]);
                    mma_bf16(aw[mt][nt], ph_[mt], vl_[nt]);
                    mma_bf16(aw[mt][nt], pl_[mt], vh_[nt]);
                }
        }
        __syncthreads();
    }

    // ---- epilogue: divide by row sum, split-write to g_ah/g_al ----
    #pragma unroll
    for (int mt = 0; mt < 2; mt++) {
        int r0 = wm + (mt << 4) + (lane >> 2);
        float ri0 = 1.0f / rsum[r0];
        float ri1 = 1.0f / rsum[r0 + 8];
        int m0 = t0 + r0;
        #pragma unroll
        for (int nt = 0; nt < 4; nt++) {
            int n0 = wnv + (nt << 3) + ((lane & 3) << 1);
            size_t o0 = (size_t)(b * T_ + m0) * D_ + h * HD_ + n0;
            size_t o1 = (size_t)(b * T_ + m0 + 8) * D_ + h * HD_ + n0;
            uint32_t hh, ll;
            split2(aw[mt][nt][0] * ri0, aw[mt][nt][1] * ri0, hh, ll);
            *(uint32_t*)&g_ah[o0] = hh; *(uint32_t*)&g_al[o0] = ll;
            split2(aw[mt][nt][2] * ri1, aw[mt][nt][3] * ri1, hh, ll);
            *(uint32_t*)&g_ah[o1] = hh; *(uint32_t*)&g_al[o1] = ll;
        }
    }

    // ---- masked region fill: cols [t0+128, T) ----
    int c0 = t0 + 128;
    if (c0 < T_) {
        int cols4 = (T_ - c0) >> 2;
        int tot = cols4 << 7;
        float4 mv = make_float4(-1e9f, -1e9f, -1e9f, -1e9f);
        for (int i = tid; i < tot; i += 256) {
            int r = i / cols4;
            int c = c0 + ((i - r * cols4) << 2);
            *(float4*)&qkout[((size_t)bh * T_ + t0 + r) * T_ + c] = mv;
        }
    }
}

// ---------------------------------------------------------------------------
extern "C" void kernel_launch(void* const* d_in, const int* in_sizes, int n_in,
                              void* d_out, int out_size)
{
    const float* x    = (const float*)d_in[0];
    const float* cosp = (const float*)d_in[2];
    const float* sinp = (const float*)d_in[3];
    const float* Wq   = (const float*)d_in[4];
    const float* bq   = (const float*)d_in[5];
    const float* Wk   = (const float*)d_in[6];
    const float* Wv   = (const float*)d_in[7];
    const float* bv   = (const float*)d_in[8];
    const float* Wo   = (const float*)d_in[9];
    const float* bo   = (const float*)d_in[10];

    float* out = (float*)d_out;
    float* qk  = out + (size_t)M_ * D_;

    static bool attr_done = false;
    if (!attr_done) {
        cudaFuncSetAttribute(gemm_tc, cudaFuncAttributeMaxDynamicSharedMemorySize,
                             2 * STGB);
        cudaFuncSetAttribute(att_fused, cudaFuncAttributeMaxDynamicSharedMemorySize,
                             ATT_SMEM);
        attr_done = true;
    }
    const int gsm = 2 * STGB;

    __nv_bfloat16 *xh, *xl, *qh_, *ql_, *kh_, *kl_, *vh_, *vl_, *ah_, *al_;
    __nv_bfloat16 *wqh, *wql, *wkh, *wkl, *wvh, *wvl, *woh, *wol;
    float *gq, *gk;
    cudaGetSymbolAddress((void**)&xh,  g_xh); cudaGetSymbolAddress((void**)&xl,  g_xl);
    cudaGetSymbolAddress((void**)&qh_, g_qh); cudaGetSymbolAddress((void**)&ql_, g_ql);
    cudaGetSymbolAddress((void**)&kh_, g_kh); cudaGetSymbolAddress((void**)&kl_, g_kl);
    cudaGetSymbolAddress((void**)&vh_, g_vh); cudaGetSymbolAddress((void**)&vl_, g_vl);
    cudaGetSymbolAddress((void**)&ah_, g_ah); cudaGetSymbolAddress((void**)&al_, g_al);
    cudaGetSymbolAddress((void**)&wqh, w_qh); cudaGetSymbolAddress((void**)&wql, w_ql);
    cudaGetSymbolAddress((void**)&wkh, w_kh); cudaGetSymbolAddress((void**)&wkl, w_kl);
    cudaGetSymbolAddress((void**)&wvh, w_vh); cudaGetSymbolAddress((void**)&wvl, w_vl);
    cudaGetSymbolAddress((void**)&woh, w_oh); cudaGetSymbolAddress((void**)&wol, w_ol);
    cudaGetSymbolAddress((void**)&gq,  g_q);  cudaGetSymbolAddress((void**)&gk,  g_k);

    presplit<<<(M_*D_/4 + 255)/256, 256>>>(x,  xh,  xl,  M_*D_/4);
    presplit<<<(D_*D_/4 + 255)/256, 256>>>(Wq, wqh, wql, D_*D_/4);
    presplit<<<(D_*D_/4 + 255)/256, 256>>>(Wk, wkh, wkl, D_*D_/4);
    presplit<<<(D_*D_/4 + 255)/256, 256>>>(Wv, wvh, wvl, D_*D_/4);
    presplit<<<(D_*D_/4 + 255)/256, 256>>>(Wo, woh, wol, D_*D_/4);

    dim3 gg(D_ / 64, M_ / 128);
    gemm_tc<<<gg, 256, gsm>>>(xh, xl, wqh, wql, bq,      gq,   nullptr, nullptr);
    gemm_tc<<<gg, 256, gsm>>>(xh, xl, wkh, wkl, nullptr, gk,   nullptr, nullptr);
    gemm_tc<<<gg, 256, gsm>>>(xh, xl, wvh, wvl, bv,      nullptr, vh_, vl_);

    rope_split<<<M_ * 512 / 256, 256>>>(gq, qh_, ql_, cosp, sinp);
    rope_split<<<M_ * 512 / 256, 256>>>(gk, kh_, kl_, cosp, sinp);

    att_fused<<<dim3(T_ / 128, B_ * H_), 256, ATT_SMEM>>>(qk);

    gemm_tc<<<gg, 256, gsm>>>(ah_, al_, woh, wol, bo, out, nullptr, nullptr);
}